// round 4
// baseline (speedup 1.0000x reference)
#include <cuda_runtime.h>
#include <cuda_bf16.h>
#include <cuda_fp16.h>
#include <math.h>
#include <stdint.h>

// ---------------- problem constants ----------------
#define BATCH   4
#define SEQ     4096
#define HID     1024
#define NHEAD   16
#define HD      64
#define CSZ     16
#define MROWS   (BATCH*SEQ)        // 16384
#define NCHUNK  (SEQ/CSZ)          // 256
#define BNCH    (BATCH*NCHUNK)     // 1024
#define KTOT    2048               // 2 * HID (fp16 hi|lo split; B side hi|hi)
#define BK      64                 // fp16 K per stage (128 bytes/row)
#define KI      (KTOT/BK)          // 32
#define NSTG    4
#define STG_BYTES 32768            // A 16KB + B 16KB
#define GEMM_SMEM (NSTG*STG_BYTES) // 128 KB

// ---------------- scratch (static device globals) ----------------
__device__ __align__(16) __half g_Abuf[(size_t)MROWS*KTOT]; // 64 MB
__device__ __align__(16) __half g_Bbuf[(size_t)HID*KTOT];   // 4 MB
__device__ float g_xp[MROWS*HID];
__device__ float g_xn[MROWS*HID];
__device__ float g_contrib[MROWS*HID];
__device__ float g_a[MROWS*NHEAD];
__device__ float g_beta[MROWS*NHEAD];
__device__ float g_cum[MROWS*NHEAD];
__device__ float g_C[BNCH*NHEAD];
__device__ float g_E[BNCH*HID];
__device__ float g_carry[BNCH*HID];
__device__ float g_P2[BATCH*HID*16];
__device__ float g_E2[BATCH*HID*16];
__device__ float g_G2[BATCH*HID*16];

// ---------------- PTX helpers (sm_80-level: compile-safe on compute_103) ----------------
__device__ __forceinline__ uint32_t smem_u32(const void* p) {
    uint32_t a;
    asm("{ .reg .u64 t; cvta.to.shared.u64 t, %1; cvt.u32.u64 %0, t; }" : "=r"(a) : "l"(p));
    return a;
}
#define CP_COMMIT() asm volatile("cp.async.commit_group;" ::: "memory")
#define CP_WAIT(N)  asm volatile("cp.async.wait_group %0;" :: "n"(N) : "memory")
__device__ __forceinline__ void cp_async16(uint32_t s, const void* g) {
    asm volatile("cp.async.cg.shared.global [%0], [%1], 16;" :: "r"(s), "l"(g) : "memory");
}
__device__ __forceinline__ void ldsm_x4(uint32_t& r0, uint32_t& r1, uint32_t& r2, uint32_t& r3, uint32_t addr) {
    asm volatile("ldmatrix.sync.aligned.m8n8.x4.shared.b16 {%0,%1,%2,%3}, [%4];"
                 : "=r"(r0), "=r"(r1), "=r"(r2), "=r"(r3) : "r"(addr));
}
__device__ __forceinline__ void mma16816(float& c0, float& c1, float& c2, float& c3,
                                         uint32_t a0, uint32_t a1, uint32_t a2, uint32_t a3,
                                         uint32_t b0, uint32_t b1) {
    asm volatile("mma.sync.aligned.m16n8k16.row.col.f32.f16.f16.f32 "
                 "{%0,%1,%2,%3}, {%4,%5,%6,%7}, {%8,%9}, {%0,%1,%2,%3};"
                 : "+f"(c0), "+f"(c1), "+f"(c2), "+f"(c3)
                 : "r"(a0), "r"(a1), "r"(a2), "r"(a3), "r"(b0), "r"(b1));
}
// xor-swizzle for 128B rows: chunk(bits 4-6) ^= row(bits 7-9)
__device__ __forceinline__ uint32_t swz(uint32_t off) { return off ^ ((off >> 3) & 0x70); }

// ---------------- fp32 -> fp16 split-pair conversion ----------------
// MODE 0 (A side): cols [0..1023]=hi, [1024..2047]=lo   (A exactly = hi+lo)
// MODE 1 (B side): cols [0..1023]=hi, [1024..2047]=hi   (B approximated by hi)
template<int MODE>
__global__ __launch_bounds__(256) void convert_pair_kernel(
    const float* __restrict__ in, __half* __restrict__ out)
{
    int g = blockIdx.x * 256 + threadIdx.x;       // float4 index
    int row = g >> 8;
    int c0  = (g & 255) << 2;
    float4 v = reinterpret_cast<const float4*>(in)[g];
    float f[4] = {v.x, v.y, v.z, v.w};
    union { __half h[4]; uint2 u; } H, L;
#pragma unroll
    for (int i = 0; i < 4; i++) {
        H.h[i] = __float2half_rn(f[i]);
        L.h[i] = __float2half_rn(f[i] - __half2float(H.h[i]));
    }
    size_t base = (size_t)row * KTOT + c0;
    *reinterpret_cast<uint2*>(out + base)        = H.u;
    *reinterpret_cast<uint2*>(out + base + 1024) = (MODE == 0) ? L.u : H.u;
}

// ---------------- mma.sync fp16 GEMM: C[m,n] = sum_k A[m,k]*B[n,k], K=2048 ----------------
// 128x128 tile, BK=64, 4-stage cp.async, 256 threads (8 warps, 32x64 each).
__device__ __forceinline__ void load_stage(const __half* Ag, const __half* Bg,
                                           uint32_t stage_base, int tid, int kit) {
    const __half* Ak = Ag + kit * BK;
    const __half* Bk = Bg + kit * BK;
    uint32_t sa = stage_base;
    uint32_t sbb = stage_base + 16384;
#pragma unroll
    for (int i = 0; i < 4; i++) {
        int u = tid + i * 256;          // 0..1023
        int row = u >> 3, c = u & 7;
        uint32_t off = swz((uint32_t)(row * 128 + c * 16));
        cp_async16(sa  + off, Ak + (size_t)row * KTOT + c * 8);
        cp_async16(sbb + off, Bk + (size_t)row * KTOT + c * 8);
    }
}

__global__ __launch_bounds__(256) void mma_gemm_kernel(
    const __half* __restrict__ A, const __half* __restrict__ B,
    float* __restrict__ C)
{
    extern __shared__ char smem[];
    const uint32_t sb = smem_u32(smem);
    const int tid = threadIdx.x, wid = tid >> 5, lane = tid & 31;
    const int m0 = blockIdx.y * 128;
    const int n0 = blockIdx.x * 128;
    const int warpM = (wid & 3) * 32;
    const int warpN = (wid >> 2) * 64;

    const __half* Ag = A + (size_t)m0 * KTOT;
    const __half* Bg = B + (size_t)n0 * KTOT;

    float acc[2][8][4];
#pragma unroll
    for (int mi = 0; mi < 2; mi++)
#pragma unroll
        for (int ni = 0; ni < 8; ni++)
#pragma unroll
            for (int q = 0; q < 4; q++) acc[mi][ni][q] = 0.f;

    // ldmatrix lane address components (row part fixed per lane)
    const int arow = warpM + (lane & 15);            // A: rows m
    const int brow = warpN + (lane & 7) + ((lane >> 4) << 3); // B: n, +8 for upper half
    const uint32_t acol_base = (uint32_t)((lane >> 4) << 4);       // 0 or 16 bytes
    const uint32_t bcol_base = (uint32_t)(((lane >> 3) & 1) << 4); // 0 or 16 bytes

#pragma unroll
    for (int s = 0; s < NSTG - 1; s++) { load_stage(Ag, Bg, sb + s * STG_BYTES, tid, s); CP_COMMIT(); }

    for (int it = 0; it < KI; it++) {
        if (it + NSTG - 1 < KI)
            load_stage(Ag, Bg, sb + ((it + NSTG - 1) & 3) * STG_BYTES, tid, it + NSTG - 1);
        CP_COMMIT();
        CP_WAIT(NSTG - 1);
        __syncthreads();

        const uint32_t sa  = sb + (it & 3) * STG_BYTES;
        const uint32_t sbb = sa + 16384;
#pragma unroll
        for (int kk = 0; kk < 4; kk++) {
            const uint32_t kByte = (uint32_t)(kk * 32);
            uint32_t a[2][4];
#pragma unroll
            for (int mi = 0; mi < 2; mi++) {
                uint32_t off = swz((uint32_t)((arow + mi * 16) * 128) + kByte + acol_base);
                ldsm_x4(a[mi][0], a[mi][1], a[mi][2], a[mi][3], sa + off);
            }
            uint32_t b[8][2];
#pragma unroll
            for (int nb = 0; nb < 4; nb++) {
                uint32_t off = swz((uint32_t)((brow + nb * 16) * 128) + kByte + bcol_base);
                uint32_t r0, r1, r2, r3;
                ldsm_x4(r0, r1, r2, r3, sbb + off);
                b[nb * 2][0] = r0; b[nb * 2][1] = r1;
                b[nb * 2 + 1][0] = r2; b[nb * 2 + 1][1] = r3;
            }
#pragma unroll
            for (int mi = 0; mi < 2; mi++)
#pragma unroll
                for (int ni = 0; ni < 8; ni++)
                    mma16816(acc[mi][ni][0], acc[mi][ni][1], acc[mi][ni][2], acc[mi][ni][3],
                             a[mi][0], a[mi][1], a[mi][2], a[mi][3], b[ni][0], b[ni][1]);
        }
        __syncthreads();
    }

    // epilogue: c frag -> C ;  c0,c1 at (row=t/4, col=2*(t%4)), c2,c3 at row+8
    const int crow = m0 + warpM + (lane >> 2);
    const int ccol = n0 + warpN + 2 * (lane & 3);
#pragma unroll
    for (int mi = 0; mi < 2; mi++)
#pragma unroll
        for (int ni = 0; ni < 8; ni++) {
            float* p0 = C + (size_t)(crow + mi * 16) * HID + ccol + ni * 8;
            float* p1 = p0 + 8 * HID;
            *reinterpret_cast<float2*>(p0) = make_float2(acc[mi][ni][0], acc[mi][ni][1]);
            *reinterpret_cast<float2*>(p1) = make_float2(acc[mi][ni][2], acc[mi][ni][3]);
        }
}

// ---------------- LayerNorm (warp per row) ----------------
__global__ __launch_bounds__(256) void ln_kernel(
    const float* __restrict__ xp, const float* __restrict__ ln_g,
    const float* __restrict__ ln_b, float* __restrict__ xn)
{
    int w = threadIdx.x >> 5, lane = threadIdx.x & 31;
    int row = blockIdx.x * 8 + w;
    const float4* xr = reinterpret_cast<const float4*>(xp + (size_t)row * HID);
    float4 v[8];
    float s = 0.f, s2 = 0.f;
#pragma unroll
    for (int i = 0; i < 8; i++) {
        v[i] = xr[lane + 32 * i];
        s  += v[i].x + v[i].y + v[i].z + v[i].w;
        s2 += v[i].x*v[i].x + v[i].y*v[i].y + v[i].z*v[i].z + v[i].w*v[i].w;
    }
#pragma unroll
    for (int o = 16; o > 0; o >>= 1) {
        s  += __shfl_xor_sync(0xffffffffu, s, o);
        s2 += __shfl_xor_sync(0xffffffffu, s2, o);
    }
    float mu = s * (1.f / HID);
    float rs = rsqrtf(s2 * (1.f / HID) - mu * mu + 1e-5f);
    float4* xo = reinterpret_cast<float4*>(xn + (size_t)row * HID);
#pragma unroll
    for (int i = 0; i < 8; i++) {
        int idx = lane + 32 * i;
        float4 g4 = reinterpret_cast<const float4*>(ln_g)[idx];
        float4 b4 = reinterpret_cast<const float4*>(ln_b)[idx];
        float4 o;
        o.x = (v[i].x - mu) * rs * g4.x + b4.x;
        o.y = (v[i].y - mu) * rs * g4.y + b4.y;
        o.z = (v[i].z - mu) * rs * g4.z + b4.z;
        o.w = (v[i].w - mu) * rs * g4.w + b4.w;
        xo[idx] = o;
    }
}

// ---------------- gates: [128 rows x 32 gates] per block, Wg tiled in SMEM ----------------
__global__ __launch_bounds__(256) void gates_kernel(
    const float* __restrict__ xn, const float* __restrict__ Wg,
    const float* __restrict__ bg, const float* __restrict__ eig,
    float* __restrict__ a_out, float* __restrict__ beta_out)
{
    __shared__ float As[32][128];
    __shared__ float Bs[32][32];
    const int tid = threadIdx.x;
    const int m0 = blockIdx.x * 128;
    const int tr = tid >> 4, tc = tid & 15;
    float acc[8][2];
#pragma unroll
    for (int i = 0; i < 8; i++) { acc[i][0] = 0.f; acc[i][1] = 0.f; }

    for (int k0 = 0; k0 < HID; k0 += 32) {
#pragma unroll
        for (int i = 0; i < 4; i++) {
            int u = tid + i * 256;
            int row = u >> 3, c4 = u & 7;
            float4 vv = *reinterpret_cast<const float4*>(xn + (size_t)(m0 + row) * HID + k0 + c4 * 4);
            As[c4*4+0][row] = vv.x; As[c4*4+1][row] = vv.y;
            As[c4*4+2][row] = vv.z; As[c4*4+3][row] = vv.w;
        }
        {
            int gr = tid >> 3, c4 = tid & 7;
            float4 vv = *reinterpret_cast<const float4*>(Wg + (size_t)gr * HID + k0 + c4 * 4);
            Bs[c4*4+0][gr] = vv.x; Bs[c4*4+1][gr] = vv.y;
            Bs[c4*4+2][gr] = vv.z; Bs[c4*4+3][gr] = vv.w;
        }
        __syncthreads();
#pragma unroll
        for (int k = 0; k < 32; k++) {
            float4 a0 = *reinterpret_cast<float4*>(&As[k][tr*8]);
            float4 a1 = *reinterpret_cast<float4*>(&As[k][tr*8+4]);
            float b0 = Bs[k][tc*2], b1 = Bs[k][tc*2+1];
            float rm[8] = {a0.x,a0.y,a0.z,a0.w,a1.x,a1.y,a1.z,a1.w};
#pragma unroll
            for (int i = 0; i < 8; i++) {
                acc[i][0] = fmaf(rm[i], b0, acc[i][0]);
                acc[i][1] = fmaf(rm[i], b1, acc[i][1]);
            }
        }
        __syncthreads();
    }
#pragma unroll
    for (int j = 0; j < 2; j++) {
        int g = tc * 2 + j;
        float bgv = bg[g];
#pragma unroll
        for (int i = 0; i < 8; i++) {
            int row = m0 + tr * 8 + i;
            float sg = 1.f / (1.f + expf(-(acc[i][j] + bgv)));
            if (g < 16) a_out[(size_t)row * NHEAD + g] = tanhf(eig[g]) * sg;
            else        beta_out[(size_t)row * NHEAD + (g - 16)] = sg;
        }
    }
}

// ---------------- scan pass 1: per-chunk contribution with reference masking ----------------
__global__ __launch_bounds__(64) void scan1_kernel(
    const float* __restrict__ a_buf, const float* __restrict__ beta_buf,
    const float* __restrict__ xn,
    float* __restrict__ contrib, float* __restrict__ cum_out,
    float* __restrict__ Cc, float* __restrict__ Ee)
{
    const int blk = blockIdx.x;
    const int h   = blk & 15;
    const int bn  = blk >> 4;
    const int base_pos = bn * CSZ;
    const int d = threadIdx.x;

    __shared__ float s_a[CSZ], s_cum[CSZ], s_inv[CSZ], s_beta[CSZ];
    if (d < CSZ) {
        s_a[d]    = a_buf[(size_t)(base_pos + d) * NHEAD + h];
        s_beta[d] = beta_buf[(size_t)(base_pos + d) * NHEAD + h];
    }
    __syncthreads();
    if (d == 0) {
        float c = 1.f;
#pragma unroll
        for (int j = 0; j < CSZ; j++) {
            float cp = c;
            c = c * s_a[j];
            s_cum[j] = c;
            s_inv[j] = (fabsf(cp) > 1e-8f) ? (1.f / cp) : 0.f;
        }
    }
    __syncthreads();
    if (d < CSZ) cum_out[(size_t)(base_pos + d) * NHEAD + h] = s_cum[d];

    float Q = 0.f, hc = 0.f;
#pragma unroll
    for (int j = 0; j < CSZ; j++) {
        size_t idx = (size_t)(base_pos + j) * HID + h * HD + d;
        float bv = s_beta[j] * xn[idx];
        hc = fmaf(s_cum[j], Q, bv);
        contrib[idx] = hc;
        Q = fmaf(bv, s_inv[j], Q);
    }
    Ee[(size_t)bn * HID + h * HD + d] = hc;
    if (d == 0) Cc[(size_t)bn * NHEAD + h] = s_cum[CSZ - 1];
}

// ---------------- scan pass 2: 3-phase group scan over 256 chunks ----------------
__global__ __launch_bounds__(256) void scan2a_kernel(
    const float* __restrict__ Cc, const float* __restrict__ Ee,
    float* __restrict__ P2, float* __restrict__ E2)
{
    int idx = blockIdx.x * 256 + threadIdx.x;   // 65536
    int ch = idx & 4095, grp = idx >> 12;
    int b = ch >> 10, c = ch & 1023, h = c >> 6;
    float P = 1.f, E = 0.f;
#pragma unroll
    for (int i = 0; i < 16; i++) {
        int bn = b * NCHUNK + grp * 16 + i;
        float cc = Cc[(size_t)bn * NHEAD + h];
        E = fmaf(cc, E, Ee[(size_t)bn * HID + c]);
        P *= cc;
    }
    P2[idx] = P; E2[idx] = E;
}
__global__ __launch_bounds__(128) void scan2b_kernel(
    const float* __restrict__ P2, const float* __restrict__ E2, float* __restrict__ G2)
{
    int ch = blockIdx.x * 128 + threadIdx.x;    // 4096
    float car = 0.f;
#pragma unroll
    for (int g = 0; g < 16; g++) {
        G2[g * 4096 + ch] = car;
        car = fmaf(P2[g * 4096 + ch], car, E2[g * 4096 + ch]);
    }
}
__global__ __launch_bounds__(256) void scan2c_kernel(
    const float* __restrict__ Cc, const float* __restrict__ Ee,
    const float* __restrict__ G2, float* __restrict__ carry)
{
    int idx = blockIdx.x * 256 + threadIdx.x;
    int ch = idx & 4095, grp = idx >> 12;
    int b = ch >> 10, c = ch & 1023, h = c >> 6;
    float car = G2[grp * 4096 + ch];
#pragma unroll
    for (int i = 0; i < 16; i++) {
        int bn = b * NCHUNK + grp * 16 + i;
        carry[(size_t)bn * HID + c] = car;
        car = fmaf(Cc[(size_t)bn * NHEAD + h], car, Ee[(size_t)bn * HID + c]);
    }
}

// ---------------- scan pass 3: h = cum*carry + contrib -> fp16 pair + h_final ----------------
__global__ __launch_bounds__(256) void scan3_kernel(
    const float* __restrict__ cum, const float* __restrict__ carry,
    const float* __restrict__ contrib,
    __half* __restrict__ Abuf, float* __restrict__ h_final)
{
    int g = blockIdx.x * 256 + threadIdx.x;     // float4 index
    int pos = g >> 8;
    int c0  = (g & 255) << 2;
    int h   = c0 >> 6;
    int bn  = pos >> 4;

    float cm = cum[(size_t)pos * NHEAD + h];
    float4 cr = reinterpret_cast<const float4*>(carry + (size_t)bn * HID)[c0 >> 2];
    float4 hv = reinterpret_cast<const float4*>(contrib)[g];
    hv.x = fmaf(cm, cr.x, hv.x);
    hv.y = fmaf(cm, cr.y, hv.y);
    hv.z = fmaf(cm, cr.z, hv.z);
    hv.w = fmaf(cm, cr.w, hv.w);

    float f[4] = {hv.x, hv.y, hv.z, hv.w};
    union { __half h[4]; uint2 u; } H, L;
#pragma unroll
    for (int i = 0; i < 4; i++) {
        H.h[i] = __float2half_rn(f[i]);
        L.h[i] = __float2half_rn(f[i] - __half2float(H.h[i]));
    }
    size_t base = (size_t)pos * KTOT + c0;
    *reinterpret_cast<uint2*>(Abuf + base)        = H.u;
    *reinterpret_cast<uint2*>(Abuf + base + 1024) = L.u;

    if ((pos & (SEQ - 1)) == SEQ - 1) {
        int b = pos >> 12;
        reinterpret_cast<float4*>(h_final + (size_t)b * HID)[c0 >> 2] = hv;
    }
}

// ---------------- launch ----------------
extern "C" void kernel_launch(void* const* d_in, const int* in_sizes, int n_in,
                              void* d_out, int out_size)
{
    const float* x       = (const float*)d_in[0];
    const float* W_in    = (const float*)d_in[1];
    const float* ln_g    = (const float*)d_in[2];
    const float* ln_b    = (const float*)d_in[3];
    const float* W_gate  = (const float*)d_in[4];
    const float* b_gate  = (const float*)d_in[5];
    const float* eig_raw = (const float*)d_in[6];
    const float* W_out   = (const float*)d_in[7];

    float* out     = (float*)d_out;
    float* h_final = out + (size_t)MROWS * HID;

    __half *Abuf, *Bbuf;
    float *xp, *xn, *contrib, *ab, *bb, *cum, *Cc, *Ee, *carry, *P2, *E2, *G2;
    cudaGetSymbolAddress((void**)&Abuf,    g_Abuf);
    cudaGetSymbolAddress((void**)&Bbuf,    g_Bbuf);
    cudaGetSymbolAddress((void**)&xp,      g_xp);
    cudaGetSymbolAddress((void**)&xn,      g_xn);
    cudaGetSymbolAddress((void**)&contrib, g_contrib);
    cudaGetSymbolAddress((void**)&ab,      g_a);
    cudaGetSymbolAddress((void**)&bb,      g_beta);
    cudaGetSymbolAddress((void**)&cum,     g_cum);
    cudaGetSymbolAddress((void**)&Cc,      g_C);
    cudaGetSymbolAddress((void**)&Ee,      g_E);
    cudaGetSymbolAddress((void**)&carry,   g_carry);
    cudaGetSymbolAddress((void**)&P2,      g_P2);
    cudaGetSymbolAddress((void**)&E2,      g_E2);
    cudaGetSymbolAddress((void**)&G2,      g_G2);

    cudaFuncSetAttribute(mma_gemm_kernel, cudaFuncAttributeMaxDynamicSharedMemorySize, GEMM_SMEM);

    // 1) convert x and W_in to fp16 split pairs, GEMM1 -> xp
    convert_pair_kernel<0><<<MROWS, 256>>>(x, Abuf);
    convert_pair_kernel<1><<<HID, 256>>>(W_in, Bbuf);
    mma_gemm_kernel<<<dim3(HID / 128, MROWS / 128), 256, GEMM_SMEM>>>(Abuf, Bbuf, xp);

    // 2) LN, gates
    ln_kernel<<<MROWS / 8, 256>>>(xp, ln_g, ln_b, xn);
    gates_kernel<<<MROWS / 128, 256>>>(xn, W_gate, b_gate, eig_raw, ab, bb);

    // 3) chunked scan (reference masking) -> fp16 pair of h_all + h_final
    scan1_kernel<<<BNCH * NHEAD, 64>>>(ab, bb, xn, contrib, cum, Cc, Ee);
    scan2a_kernel<<<(BATCH * HID * 16) / 256, 256>>>(Cc, Ee, P2, E2);
    scan2b_kernel<<<(BATCH * HID) / 128, 128>>>(P2, E2, G2);
    scan2c_kernel<<<(BATCH * HID * 16) / 256, 256>>>(Cc, Ee, G2, carry);
    scan3_kernel<<<MROWS, 256>>>(cum, carry, contrib, Abuf, h_final);

    // 4) GEMM2 -> out
    convert_pair_kernel<1><<<HID, 256>>>(W_out, Bbuf);
    mma_gemm_kernel<<<dim3(HID / 128, MROWS / 128), 256, GEMM_SMEM>>>(Abuf, Bbuf, out);
}

// round 5
// speedup vs baseline: 2.1996x; 2.1996x over previous
#include <cuda_runtime.h>
#include <cuda_fp16.h>
#include <math.h>
#include <stdint.h>

// ---------------- problem constants ----------------
#define BATCH   4
#define SEQ     4096
#define HID     1024
#define NHEAD   16
#define HD      64
#define CSZ     16
#define MROWS   (BATCH*SEQ)        // 16384
#define NCHUNK  (SEQ/CSZ)          // 256
#define BNCH    (BATCH*NCHUNK)     // 1024
#define KTOT    1024               // single fp16 pass
#define BK      64                 // fp16 K per stage (128 bytes/row)
#define KI      (KTOT/BK)          // 16
#define NSTG    4
#define STG_BYTES 32768            // A 16KB + B 16KB
#define GEMM_SMEM (NSTG*STG_BYTES) // 128 KB

// ---------------- scratch (static device globals) ----------------
__device__ __align__(16) __half g_Abuf[(size_t)MROWS*KTOT]; // 32 MB
__device__ __align__(16) __half g_Bbuf[(size_t)HID*KTOT];   // 2 MB
__device__ float g_xp[MROWS*HID];
__device__ float g_xn[MROWS*HID];
__device__ float g_contrib[MROWS*HID];
__device__ float g_a[MROWS*NHEAD];
__device__ float g_beta[MROWS*NHEAD];
__device__ float g_cum[MROWS*NHEAD];
__device__ float g_C[BNCH*NHEAD];
__device__ float g_E[BNCH*HID];
__device__ float g_carry[BNCH*HID];
__device__ float g_P2[BATCH*HID*16];
__device__ float g_E2[BATCH*HID*16];
__device__ float g_G2[BATCH*HID*16];

// ---------------- PTX helpers (sm_80-level: compile-safe on compute_103) ----------------
__device__ __forceinline__ uint32_t smem_u32(const void* p) {
    uint32_t a;
    asm("{ .reg .u64 t; cvta.to.shared.u64 t, %1; cvt.u32.u64 %0, t; }" : "=r"(a) : "l"(p));
    return a;
}
#define CP_COMMIT() asm volatile("cp.async.commit_group;" ::: "memory")
#define CP_WAIT(N)  asm volatile("cp.async.wait_group %0;" :: "n"(N) : "memory")
__device__ __forceinline__ void cp_async16(uint32_t s, const void* g) {
    asm volatile("cp.async.cg.shared.global [%0], [%1], 16;" :: "r"(s), "l"(g) : "memory");
}
__device__ __forceinline__ void ldsm_x4(uint32_t& r0, uint32_t& r1, uint32_t& r2, uint32_t& r3, uint32_t addr) {
    asm volatile("ldmatrix.sync.aligned.m8n8.x4.shared.b16 {%0,%1,%2,%3}, [%4];"
                 : "=r"(r0), "=r"(r1), "=r"(r2), "=r"(r3) : "r"(addr));
}
__device__ __forceinline__ void mma16816(float& c0, float& c1, float& c2, float& c3,
                                         uint32_t a0, uint32_t a1, uint32_t a2, uint32_t a3,
                                         uint32_t b0, uint32_t b1) {
    asm volatile("mma.sync.aligned.m16n8k16.row.col.f32.f16.f16.f32 "
                 "{%0,%1,%2,%3}, {%4,%5,%6,%7}, {%8,%9}, {%0,%1,%2,%3};"
                 : "+f"(c0), "+f"(c1), "+f"(c2), "+f"(c3)
                 : "r"(a0), "r"(a1), "r"(a2), "r"(a3), "r"(b0), "r"(b1));
}
// xor-swizzle for 128B rows: chunk(bits 4-6) ^= row(bits 7-9)
__device__ __forceinline__ uint32_t swz(uint32_t off) { return off ^ ((off >> 3) & 0x70); }

// ---------------- fp32 -> fp16 conversion (plain) ----------------
__global__ __launch_bounds__(256) void convert_half_kernel(
    const float* __restrict__ in, __half* __restrict__ out)
{
    int g = blockIdx.x * 256 + threadIdx.x;       // float4 index
    float4 v = reinterpret_cast<const float4*>(in)[g];
    union { __half h[4]; uint2 u; } H;
    H.h[0] = __float2half_rn(v.x);
    H.h[1] = __float2half_rn(v.y);
    H.h[2] = __float2half_rn(v.z);
    H.h[3] = __float2half_rn(v.w);
    reinterpret_cast<uint2*>(out)[g] = H.u;
}

// ---------------- mma.sync fp16 GEMM: C[m,n] = sum_k A[m,k]*B[n,k], K=1024 ----------------
// 128x128 tile, BK=64, 4-stage cp.async, 256 threads (8 warps, 32x64 each).
__device__ __forceinline__ void load_stage(const __half* Ag, const __half* Bg,
                                           uint32_t stage_base, int tid, int kit) {
    const __half* Ak = Ag + kit * BK;
    const __half* Bk = Bg + kit * BK;
    uint32_t sa = stage_base;
    uint32_t sbb = stage_base + 16384;
#pragma unroll
    for (int i = 0; i < 4; i++) {
        int u = tid + i * 256;          // 0..1023
        int row = u >> 3, c = u & 7;
        uint32_t off = swz((uint32_t)(row * 128 + c * 16));
        cp_async16(sa  + off, Ak + (size_t)row * KTOT + c * 8);
        cp_async16(sbb + off, Bk + (size_t)row * KTOT + c * 8);
    }
}

__global__ __launch_bounds__(256) void mma_gemm_kernel(
    const __half* __restrict__ A, const __half* __restrict__ B,
    float* __restrict__ C)
{
    extern __shared__ char smem[];
    const uint32_t sb = smem_u32(smem);
    const int tid = threadIdx.x, wid = tid >> 5, lane = tid & 31;
    const int m0 = blockIdx.y * 128;
    const int n0 = blockIdx.x * 128;
    const int warpM = (wid & 3) * 32;
    const int warpN = (wid >> 2) * 64;

    const __half* Ag = A + (size_t)m0 * KTOT;
    const __half* Bg = B + (size_t)n0 * KTOT;

    float acc[2][8][4];
#pragma unroll
    for (int mi = 0; mi < 2; mi++)
#pragma unroll
        for (int ni = 0; ni < 8; ni++)
#pragma unroll
            for (int q = 0; q < 4; q++) acc[mi][ni][q] = 0.f;

    // ldmatrix lane address components (row part fixed per lane)
    const int arow = warpM + (lane & 15);            // A: rows m
    const int brow = warpN + (lane & 7) + ((lane >> 4) << 3); // B: n, +8 for upper half
    const uint32_t acol_base = (uint32_t)((lane >> 4) << 4);       // 0 or 16 bytes
    const uint32_t bcol_base = (uint32_t)(((lane >> 3) & 1) << 4); // 0 or 16 bytes

#pragma unroll
    for (int s = 0; s < NSTG - 1; s++) { load_stage(Ag, Bg, sb + s * STG_BYTES, tid, s); CP_COMMIT(); }

    for (int it = 0; it < KI; it++) {
        if (it + NSTG - 1 < KI)
            load_stage(Ag, Bg, sb + ((it + NSTG - 1) & 3) * STG_BYTES, tid, it + NSTG - 1);
        CP_COMMIT();
        CP_WAIT(NSTG - 1);
        __syncthreads();

        const uint32_t sa  = sb + (it & 3) * STG_BYTES;
        const uint32_t sbb = sa + 16384;
#pragma unroll
        for (int kk = 0; kk < 4; kk++) {
            const uint32_t kByte = (uint32_t)(kk * 32);
            uint32_t a[2][4];
#pragma unroll
            for (int mi = 0; mi < 2; mi++) {
                uint32_t off = swz((uint32_t)((arow + mi * 16) * 128) + kByte + acol_base);
                ldsm_x4(a[mi][0], a[mi][1], a[mi][2], a[mi][3], sa + off);
            }
            uint32_t b[8][2];
#pragma unroll
            for (int nb = 0; nb < 4; nb++) {
                uint32_t off = swz((uint32_t)((brow + nb * 16) * 128) + kByte + bcol_base);
                uint32_t r0, r1, r2, r3;
                ldsm_x4(r0, r1, r2, r3, sbb + off);
                b[nb * 2][0] = r0; b[nb * 2][1] = r1;
                b[nb * 2 + 1][0] = r2; b[nb * 2 + 1][1] = r3;
            }
#pragma unroll
            for (int mi = 0; mi < 2; mi++)
#pragma unroll
                for (int ni = 0; ni < 8; ni++)
                    mma16816(acc[mi][ni][0], acc[mi][ni][1], acc[mi][ni][2], acc[mi][ni][3],
                             a[mi][0], a[mi][1], a[mi][2], a[mi][3], b[ni][0], b[ni][1]);
        }
        __syncthreads();
    }

    // epilogue: c frag -> C ;  c0,c1 at (row=t/4, col=2*(t%4)), c2,c3 at row+8
    const int crow = m0 + warpM + (lane >> 2);
    const int ccol = n0 + warpN + 2 * (lane & 3);
#pragma unroll
    for (int mi = 0; mi < 2; mi++)
#pragma unroll
        for (int ni = 0; ni < 8; ni++) {
            float* p0 = C + (size_t)(crow + mi * 16) * HID + ccol + ni * 8;
            float* p1 = p0 + 8 * HID;
            *reinterpret_cast<float2*>(p0) = make_float2(acc[mi][ni][0], acc[mi][ni][1]);
            *reinterpret_cast<float2*>(p1) = make_float2(acc[mi][ni][2], acc[mi][ni][3]);
        }
}

// ---------------- fused LayerNorm + gates (128 rows per block) ----------------
// Phase 1: 8 warps x 16 rows LN -> xn (global; visible in-block after syncthreads)
// Phase 2: tiled 128x32 gates GEMM reading xn (L1/L2 hot), sigmoid -> a, beta
__global__ __launch_bounds__(256) void lngates_kernel(
    const float* __restrict__ xp, const float* __restrict__ ln_g,
    const float* __restrict__ ln_b, float* __restrict__ xn,
    const float* __restrict__ Wg, const float* __restrict__ bg,
    const float* __restrict__ eig,
    float* __restrict__ a_out, float* __restrict__ beta_out)
{
    const int tid = threadIdx.x;
    const int m0 = blockIdx.x * 128;
    const int w = tid >> 5, lane = tid & 31;

    // ---- phase 1: LN over 16 rows per warp ----
#pragma unroll 1
    for (int rr = 0; rr < 16; rr++) {
        int row = m0 + w * 16 + rr;
        const float4* xr = reinterpret_cast<const float4*>(xp + (size_t)row * HID);
        float4 v[8];
        float s = 0.f, s2 = 0.f;
#pragma unroll
        for (int i = 0; i < 8; i++) {
            v[i] = xr[lane + 32 * i];
            s  += v[i].x + v[i].y + v[i].z + v[i].w;
            s2 += v[i].x*v[i].x + v[i].y*v[i].y + v[i].z*v[i].z + v[i].w*v[i].w;
        }
#pragma unroll
        for (int o = 16; o > 0; o >>= 1) {
            s  += __shfl_xor_sync(0xffffffffu, s, o);
            s2 += __shfl_xor_sync(0xffffffffu, s2, o);
        }
        float mu = s * (1.f / HID);
        float rs = rsqrtf(s2 * (1.f / HID) - mu * mu + 1e-5f);
        float4* xo = reinterpret_cast<float4*>(xn + (size_t)row * HID);
#pragma unroll
        for (int i = 0; i < 8; i++) {
            int idx = lane + 32 * i;
            float4 g4 = reinterpret_cast<const float4*>(ln_g)[idx];
            float4 b4 = reinterpret_cast<const float4*>(ln_b)[idx];
            float4 o;
            o.x = (v[i].x - mu) * rs * g4.x + b4.x;
            o.y = (v[i].y - mu) * rs * g4.y + b4.y;
            o.z = (v[i].z - mu) * rs * g4.z + b4.z;
            o.w = (v[i].w - mu) * rs * g4.w + b4.w;
            xo[idx] = o;
        }
    }
    __syncthreads();

    // ---- phase 2: gates GEMM [128 x 32] ----
    __shared__ float As[32][128];
    __shared__ float Bs[32][32];
    const int tr = tid >> 4, tc = tid & 15;
    float acc[8][2];
#pragma unroll
    for (int i = 0; i < 8; i++) { acc[i][0] = 0.f; acc[i][1] = 0.f; }

    for (int k0 = 0; k0 < HID; k0 += 32) {
#pragma unroll
        for (int i = 0; i < 4; i++) {
            int u = tid + i * 256;
            int row = u >> 3, c4 = u & 7;
            float4 vv = *reinterpret_cast<const float4*>(xn + (size_t)(m0 + row) * HID + k0 + c4 * 4);
            As[c4*4+0][row] = vv.x; As[c4*4+1][row] = vv.y;
            As[c4*4+2][row] = vv.z; As[c4*4+3][row] = vv.w;
        }
        {
            int gr = tid >> 3, c4 = tid & 7;
            float4 vv = *reinterpret_cast<const float4*>(Wg + (size_t)gr * HID + k0 + c4 * 4);
            Bs[c4*4+0][gr] = vv.x; Bs[c4*4+1][gr] = vv.y;
            Bs[c4*4+2][gr] = vv.z; Bs[c4*4+3][gr] = vv.w;
        }
        __syncthreads();
#pragma unroll
        for (int k = 0; k < 32; k++) {
            float4 a0 = *reinterpret_cast<float4*>(&As[k][tr*8]);
            float4 a1 = *reinterpret_cast<float4*>(&As[k][tr*8+4]);
            float b0 = Bs[k][tc*2], b1 = Bs[k][tc*2+1];
            float rm[8] = {a0.x,a0.y,a0.z,a0.w,a1.x,a1.y,a1.z,a1.w};
#pragma unroll
            for (int i = 0; i < 8; i++) {
                acc[i][0] = fmaf(rm[i], b0, acc[i][0]);
                acc[i][1] = fmaf(rm[i], b1, acc[i][1]);
            }
        }
        __syncthreads();
    }
#pragma unroll
    for (int j = 0; j < 2; j++) {
        int g = tc * 2 + j;
        float bgv = bg[g];
#pragma unroll
        for (int i = 0; i < 8; i++) {
            int row = m0 + tr * 8 + i;
            float sg = 1.f / (1.f + expf(-(acc[i][j] + bgv)));
            if (g < 16) a_out[(size_t)row * NHEAD + g] = tanhf(eig[g]) * sg;
            else        beta_out[(size_t)row * NHEAD + (g - 16)] = sg;
        }
    }
}

// ---------------- scan pass 1: per-chunk contribution with reference masking ----------------
__global__ __launch_bounds__(64) void scan1_kernel(
    const float* __restrict__ a_buf, const float* __restrict__ beta_buf,
    const float* __restrict__ xn,
    float* __restrict__ contrib, float* __restrict__ cum_out,
    float* __restrict__ Cc, float* __restrict__ Ee)
{
    const int blk = blockIdx.x;
    const int h   = blk & 15;
    const int bn  = blk >> 4;
    const int base_pos = bn * CSZ;
    const int d = threadIdx.x;

    __shared__ float s_a[CSZ], s_cum[CSZ], s_inv[CSZ], s_beta[CSZ];
    if (d < CSZ) {
        s_a[d]    = a_buf[(size_t)(base_pos + d) * NHEAD + h];
        s_beta[d] = beta_buf[(size_t)(base_pos + d) * NHEAD + h];
    }
    __syncthreads();
    if (d == 0) {
        float c = 1.f;
#pragma unroll
        for (int j = 0; j < CSZ; j++) {
            float cp = c;
            c = c * s_a[j];
            s_cum[j] = c;
            s_inv[j] = (fabsf(cp) > 1e-8f) ? (1.f / cp) : 0.f;
        }
    }
    __syncthreads();
    if (d < CSZ) cum_out[(size_t)(base_pos + d) * NHEAD + h] = s_cum[d];

    float Q = 0.f, hc = 0.f;
#pragma unroll
    for (int j = 0; j < CSZ; j++) {
        size_t idx = (size_t)(base_pos + j) * HID + h * HD + d;
        float bv = s_beta[j] * xn[idx];
        hc = fmaf(s_cum[j], Q, bv);
        contrib[idx] = hc;
        Q = fmaf(bv, s_inv[j], Q);
    }
    Ee[(size_t)bn * HID + h * HD + d] = hc;
    if (d == 0) Cc[(size_t)bn * NHEAD + h] = s_cum[CSZ - 1];
}

// ---------------- scan pass 2: 3-phase group scan over 256 chunks ----------------
__global__ __launch_bounds__(256) void scan2a_kernel(
    const float* __restrict__ Cc, const float* __restrict__ Ee,
    float* __restrict__ P2, float* __restrict__ E2)
{
    int idx = blockIdx.x * 256 + threadIdx.x;   // 65536
    int ch = idx & 4095, grp = idx >> 12;
    int b = ch >> 10, c = ch & 1023, h = c >> 6;
    float P = 1.f, E = 0.f;
#pragma unroll
    for (int i = 0; i < 16; i++) {
        int bn = b * NCHUNK + grp * 16 + i;
        float cc = Cc[(size_t)bn * NHEAD + h];
        E = fmaf(cc, E, Ee[(size_t)bn * HID + c]);
        P *= cc;
    }
    P2[idx] = P; E2[idx] = E;
}
__global__ __launch_bounds__(128) void scan2b_kernel(
    const float* __restrict__ P2, const float* __restrict__ E2, float* __restrict__ G2)
{
    int ch = blockIdx.x * 128 + threadIdx.x;    // 4096
    float car = 0.f;
#pragma unroll
    for (int g = 0; g < 16; g++) {
        G2[g * 4096 + ch] = car;
        car = fmaf(P2[g * 4096 + ch], car, E2[g * 4096 + ch]);
    }
}
__global__ __launch_bounds__(256) void scan2c_kernel(
    const float* __restrict__ Cc, const float* __restrict__ Ee,
    const float* __restrict__ G2, float* __restrict__ carry)
{
    int idx = blockIdx.x * 256 + threadIdx.x;
    int ch = idx & 4095, grp = idx >> 12;
    int b = ch >> 10, c = ch & 1023, h = c >> 6;
    float car = G2[grp * 4096 + ch];
#pragma unroll
    for (int i = 0; i < 16; i++) {
        int bn = b * NCHUNK + grp * 16 + i;
        carry[(size_t)bn * HID + c] = car;
        car = fmaf(Cc[(size_t)bn * NHEAD + h], car, Ee[(size_t)bn * HID + c]);
    }
}

// ---------------- scan pass 3: h = cum*carry + contrib -> fp16 + h_final ----------------
__global__ __launch_bounds__(256) void scan3_kernel(
    const float* __restrict__ cum, const float* __restrict__ carry,
    const float* __restrict__ contrib,
    __half* __restrict__ Abuf, float* __restrict__ h_final)
{
    int g = blockIdx.x * 256 + threadIdx.x;     // float4 index
    int pos = g >> 8;
    int c0  = (g & 255) << 2;
    int h   = c0 >> 6;
    int bn  = pos >> 4;

    float cm = cum[(size_t)pos * NHEAD + h];
    float4 cr = reinterpret_cast<const float4*>(carry + (size_t)bn * HID)[c0 >> 2];
    float4 hv = reinterpret_cast<const float4*>(contrib)[g];
    hv.x = fmaf(cm, cr.x, hv.x);
    hv.y = fmaf(cm, cr.y, hv.y);
    hv.z = fmaf(cm, cr.z, hv.z);
    hv.w = fmaf(cm, cr.w, hv.w);

    union { __half h[4]; uint2 u; } H;
    H.h[0] = __float2half_rn(hv.x);
    H.h[1] = __float2half_rn(hv.y);
    H.h[2] = __float2half_rn(hv.z);
    H.h[3] = __float2half_rn(hv.w);
    reinterpret_cast<uint2*>(Abuf)[g] = H.u;

    if ((pos & (SEQ - 1)) == SEQ - 1) {
        int b = pos >> 12;
        reinterpret_cast<float4*>(h_final + (size_t)b * HID)[c0 >> 2] = hv;
    }
}

// ---------------- launch ----------------
extern "C" void kernel_launch(void* const* d_in, const int* in_sizes, int n_in,
                              void* d_out, int out_size)
{
    const float* x       = (const float*)d_in[0];
    const float* W_in    = (const float*)d_in[1];
    const float* ln_g    = (const float*)d_in[2];
    const float* ln_b    = (const float*)d_in[3];
    const float* W_gate  = (const float*)d_in[4];
    const float* b_gate  = (const float*)d_in[5];
    const float* eig_raw = (const float*)d_in[6];
    const float* W_out   = (const float*)d_in[7];

    float* out     = (float*)d_out;
    float* h_final = out + (size_t)MROWS * HID;

    __half *Abuf, *Bbuf;
    float *xp, *xn, *contrib, *ab, *bb, *cum, *Cc, *Ee, *carry, *P2, *E2, *G2;
    cudaGetSymbolAddress((void**)&Abuf,    g_Abuf);
    cudaGetSymbolAddress((void**)&Bbuf,    g_Bbuf);
    cudaGetSymbolAddress((void**)&xp,      g_xp);
    cudaGetSymbolAddress((void**)&xn,      g_xn);
    cudaGetSymbolAddress((void**)&contrib, g_contrib);
    cudaGetSymbolAddress((void**)&ab,      g_a);
    cudaGetSymbolAddress((void**)&bb,      g_beta);
    cudaGetSymbolAddress((void**)&cum,     g_cum);
    cudaGetSymbolAddress((void**)&Cc,      g_C);
    cudaGetSymbolAddress((void**)&Ee,      g_E);
    cudaGetSymbolAddress((void**)&carry,   g_carry);
    cudaGetSymbolAddress((void**)&P2,      g_P2);
    cudaGetSymbolAddress((void**)&E2,      g_E2);
    cudaGetSymbolAddress((void**)&G2,      g_G2);

    cudaFuncSetAttribute(mma_gemm_kernel, cudaFuncAttributeMaxDynamicSharedMemorySize, GEMM_SMEM);

    // 1) convert x and W_in to fp16, GEMM1 -> xp
    convert_half_kernel<<<(MROWS * HID / 4) / 256, 256>>>(x, Abuf);
    convert_half_kernel<<<(HID * HID / 4) / 256, 256>>>(W_in, Bbuf);
    mma_gemm_kernel<<<dim3(HID / 128, MROWS / 128), 256, GEMM_SMEM>>>(Abuf, Bbuf, xp);

    // 2) fused LN + gates
    lngates_kernel<<<MROWS / 128, 256>>>(xp, ln_g, ln_b, xn, W_gate, b_gate, eig_raw, ab, bb);

    // 3) chunked scan (reference masking) -> fp16 h_all + h_final
    scan1_kernel<<<BNCH * NHEAD, 64>>>(ab, bb, xn, contrib, cum, Cc, Ee);
    scan2a_kernel<<<(BATCH * HID * 16) / 256, 256>>>(Cc, Ee, P2, E2);
    scan2b_kernel<<<(BATCH * HID) / 128, 128>>>(P2, E2, G2);
    scan2c_kernel<<<(BATCH * HID * 16) / 256, 256>>>(Cc, Ee, G2, carry);
    scan3_kernel<<<MROWS, 256>>>(cum, carry, contrib, Abuf, h_final);

    // 4) GEMM2 -> out
    convert_half_kernel<<<(HID * HID / 4) / 256, 256>>>(W_out, Bbuf);
    mma_gemm_kernel<<<dim3(HID / 128, MROWS / 128), 256, GEMM_SMEM>>>(Abuf, Bbuf, out);
}

// round 6
// speedup vs baseline: 2.5262x; 1.1485x over previous
#include <cuda_runtime.h>
#include <cuda_fp16.h>
#include <math.h>
#include <stdint.h>

// ---------------- problem constants ----------------
#define BATCH   4
#define SEQ     4096
#define HID     1024
#define NHEAD   16
#define HD      64
#define CSZ     16
#define MROWS   (BATCH*SEQ)        // 16384
#define NCHUNK  (SEQ/CSZ)          // 256
#define BNCH    (BATCH*NCHUNK)     // 1024
#define KTOT    1024               // single fp16 pass
#define BK      64                 // fp16 K per stage (128 bytes/row)
#define KI      (KTOT/BK)          // 16
#define NSTG    4
#define STG_BYTES 32768            // A 16KB + B 16KB
#define GEMM_SMEM (NSTG*STG_BYTES) // 128 KB
#define GATES_STG 20480            // A 16KB + B 4KB
#define GATES_SMEM (NSTG*GATES_STG)// 80 KB

// ---------------- scratch (static device globals) ----------------
__device__ __align__(16) __half g_Abuf[(size_t)MROWS*KTOT]; // 32 MB (x fp16 -> xn fp16 -> h fp16)
__device__ __align__(16) __half g_Bbuf[(size_t)HID*KTOT];   // 2 MB
__device__ float g_xp[MROWS*HID];
__device__ float g_xn[MROWS*HID];
__device__ float g_contrib[MROWS*HID];
__device__ float g_a[MROWS*NHEAD];
__device__ float g_beta[MROWS*NHEAD];
__device__ float g_cum[MROWS*NHEAD];
__device__ float g_C[BNCH*NHEAD];
__device__ float g_E[BNCH*HID];
__device__ float g_carry[BNCH*HID];
__device__ float g_P2[BATCH*HID*16];
__device__ float g_E2[BATCH*HID*16];
__device__ float g_G2[BATCH*HID*16];

// ---------------- PTX helpers (sm_80-level: compile-safe on compute_103) ----------------
__device__ __forceinline__ uint32_t smem_u32(const void* p) {
    uint32_t a;
    asm("{ .reg .u64 t; cvta.to.shared.u64 t, %1; cvt.u32.u64 %0, t; }" : "=r"(a) : "l"(p));
    return a;
}
#define CP_COMMIT() asm volatile("cp.async.commit_group;" ::: "memory")
#define CP_WAIT(N)  asm volatile("cp.async.wait_group %0;" :: "n"(N) : "memory")
__device__ __forceinline__ void cp_async16(uint32_t s, const void* g) {
    asm volatile("cp.async.cg.shared.global [%0], [%1], 16;" :: "r"(s), "l"(g) : "memory");
}
__device__ __forceinline__ void ldsm_x4(uint32_t& r0, uint32_t& r1, uint32_t& r2, uint32_t& r3, uint32_t addr) {
    asm volatile("ldmatrix.sync.aligned.m8n8.x4.shared.b16 {%0,%1,%2,%3}, [%4];"
                 : "=r"(r0), "=r"(r1), "=r"(r2), "=r"(r3) : "r"(addr));
}
__device__ __forceinline__ void mma16816(float& c0, float& c1, float& c2, float& c3,
                                         uint32_t a0, uint32_t a1, uint32_t a2, uint32_t a3,
                                         uint32_t b0, uint32_t b1) {
    asm volatile("mma.sync.aligned.m16n8k16.row.col.f32.f16.f16.f32 "
                 "{%0,%1,%2,%3}, {%4,%5,%6,%7}, {%8,%9}, {%0,%1,%2,%3};"
                 : "+f"(c0), "+f"(c1), "+f"(c2), "+f"(c3)
                 : "r"(a0), "r"(a1), "r"(a2), "r"(a3), "r"(b0), "r"(b1));
}
// xor-swizzle for 128B rows: chunk(bits 4-6) ^= row(bits 7-9)
__device__ __forceinline__ uint32_t swz(uint32_t off) { return off ^ ((off >> 3) & 0x70); }

// ---------------- fp32 -> fp16 conversion (plain) ----------------
__global__ __launch_bounds__(256) void convert_half_kernel(
    const float* __restrict__ in, __half* __restrict__ out)
{
    int g = blockIdx.x * 256 + threadIdx.x;       // float4 index
    float4 v = reinterpret_cast<const float4*>(in)[g];
    union { __half h[4]; uint2 u; } H;
    H.h[0] = __float2half_rn(v.x);
    H.h[1] = __float2half_rn(v.y);
    H.h[2] = __float2half_rn(v.z);
    H.h[3] = __float2half_rn(v.w);
    reinterpret_cast<uint2*>(out)[g] = H.u;
}

// ---------------- mma.sync fp16 GEMM: C[m,n] = sum_k A[m,k]*B[n,k], K=1024 ----------------
// 128x128 tile, BK=64, 4-stage cp.async, 256 threads (8 warps, 32x64 each).
__device__ __forceinline__ void load_stage(const __half* Ag, const __half* Bg,
                                           uint32_t stage_base, int tid, int kit) {
    const __half* Ak = Ag + kit * BK;
    const __half* Bk = Bg + kit * BK;
    uint32_t sa = stage_base;
    uint32_t sbb = stage_base + 16384;
#pragma unroll
    for (int i = 0; i < 4; i++) {
        int u = tid + i * 256;          // 0..1023
        int row = u >> 3, c = u & 7;
        uint32_t off = swz((uint32_t)(row * 128 + c * 16));
        cp_async16(sa  + off, Ak + (size_t)row * KTOT + c * 8);
        cp_async16(sbb + off, Bk + (size_t)row * KTOT + c * 8);
    }
}

__global__ __launch_bounds__(256) void mma_gemm_kernel(
    const __half* __restrict__ A, const __half* __restrict__ B,
    float* __restrict__ C)
{
    extern __shared__ char smem[];
    const uint32_t sb = smem_u32(smem);
    const int tid = threadIdx.x, wid = tid >> 5, lane = tid & 31;
    const int m0 = blockIdx.y * 128;
    const int n0 = blockIdx.x * 128;
    const int warpM = (wid & 3) * 32;
    const int warpN = (wid >> 2) * 64;

    const __half* Ag = A + (size_t)m0 * KTOT;
    const __half* Bg = B + (size_t)n0 * KTOT;

    float acc[2][8][4];
#pragma unroll
    for (int mi = 0; mi < 2; mi++)
#pragma unroll
        for (int ni = 0; ni < 8; ni++)
#pragma unroll
            for (int q = 0; q < 4; q++) acc[mi][ni][q] = 0.f;

    const int arow = warpM + (lane & 15);
    const int brow = warpN + (lane & 7) + ((lane >> 4) << 3);
    const uint32_t acol_base = (uint32_t)((lane >> 4) << 4);
    const uint32_t bcol_base = (uint32_t)(((lane >> 3) & 1) << 4);

#pragma unroll
    for (int s = 0; s < NSTG - 1; s++) { load_stage(Ag, Bg, sb + s * STG_BYTES, tid, s); CP_COMMIT(); }

    for (int it = 0; it < KI; it++) {
        if (it + NSTG - 1 < KI)
            load_stage(Ag, Bg, sb + ((it + NSTG - 1) & 3) * STG_BYTES, tid, it + NSTG - 1);
        CP_COMMIT();
        CP_WAIT(NSTG - 1);
        __syncthreads();

        const uint32_t sa  = sb + (it & 3) * STG_BYTES;
        const uint32_t sbb = sa + 16384;
#pragma unroll
        for (int kk = 0; kk < 4; kk++) {
            const uint32_t kByte = (uint32_t)(kk * 32);
            uint32_t a[2][4];
#pragma unroll
            for (int mi = 0; mi < 2; mi++) {
                uint32_t off = swz((uint32_t)((arow + mi * 16) * 128) + kByte + acol_base);
                ldsm_x4(a[mi][0], a[mi][1], a[mi][2], a[mi][3], sa + off);
            }
            uint32_t b[8][2];
#pragma unroll
            for (int nb = 0; nb < 4; nb++) {
                uint32_t off = swz((uint32_t)((brow + nb * 16) * 128) + kByte + bcol_base);
                uint32_t r0, r1, r2, r3;
                ldsm_x4(r0, r1, r2, r3, sbb + off);
                b[nb * 2][0] = r0; b[nb * 2][1] = r1;
                b[nb * 2 + 1][0] = r2; b[nb * 2 + 1][1] = r3;
            }
#pragma unroll
            for (int mi = 0; mi < 2; mi++)
#pragma unroll
                for (int ni = 0; ni < 8; ni++)
                    mma16816(acc[mi][ni][0], acc[mi][ni][1], acc[mi][ni][2], acc[mi][ni][3],
                             a[mi][0], a[mi][1], a[mi][2], a[mi][3], b[ni][0], b[ni][1]);
        }
        __syncthreads();
    }

    const int crow = m0 + warpM + (lane >> 2);
    const int ccol = n0 + warpN + 2 * (lane & 3);
#pragma unroll
    for (int mi = 0; mi < 2; mi++)
#pragma unroll
        for (int ni = 0; ni < 8; ni++) {
            float* p0 = C + (size_t)(crow + mi * 16) * HID + ccol + ni * 8;
            float* p1 = p0 + 8 * HID;
            *reinterpret_cast<float2*>(p0) = make_float2(acc[mi][ni][0], acc[mi][ni][1]);
            *reinterpret_cast<float2*>(p1) = make_float2(acc[mi][ni][2], acc[mi][ni][3]);
        }
}

// ---------------- LayerNorm (warp per row) -> fp32 xn + fp16 xnh ----------------
__global__ __launch_bounds__(256) void ln_kernel(
    const float* __restrict__ xp, const float* __restrict__ ln_g,
    const float* __restrict__ ln_b, float* __restrict__ xn,
    __half* __restrict__ xnh)
{
    int w = threadIdx.x >> 5, lane = threadIdx.x & 31;
    int row = blockIdx.x * 8 + w;
    const float4* xr = reinterpret_cast<const float4*>(xp + (size_t)row * HID);
    float4 v[8];
    float s = 0.f, s2 = 0.f;
#pragma unroll
    for (int i = 0; i < 8; i++) {
        v[i] = xr[lane + 32 * i];
        s  += v[i].x + v[i].y + v[i].z + v[i].w;
        s2 += v[i].x*v[i].x + v[i].y*v[i].y + v[i].z*v[i].z + v[i].w*v[i].w;
    }
#pragma unroll
    for (int o = 16; o > 0; o >>= 1) {
        s  += __shfl_xor_sync(0xffffffffu, s, o);
        s2 += __shfl_xor_sync(0xffffffffu, s2, o);
    }
    float mu = s * (1.f / HID);
    float rs = rsqrtf(s2 * (1.f / HID) - mu * mu + 1e-5f);
    float4* xo = reinterpret_cast<float4*>(xn + (size_t)row * HID);
    uint2*  xh = reinterpret_cast<uint2*>(xnh + (size_t)row * HID);
#pragma unroll
    for (int i = 0; i < 8; i++) {
        int idx = lane + 32 * i;
        float4 g4 = reinterpret_cast<const float4*>(ln_g)[idx];
        float4 b4 = reinterpret_cast<const float4*>(ln_b)[idx];
        float4 o;
        o.x = (v[i].x - mu) * rs * g4.x + b4.x;
        o.y = (v[i].y - mu) * rs * g4.y + b4.y;
        o.z = (v[i].z - mu) * rs * g4.z + b4.z;
        o.w = (v[i].w - mu) * rs * g4.w + b4.w;
        xo[idx] = o;
        union { __half h[4]; uint2 u; } H;
        H.h[0] = __float2half_rn(o.x);
        H.h[1] = __float2half_rn(o.y);
        H.h[2] = __float2half_rn(o.z);
        H.h[3] = __float2half_rn(o.w);
        xh[idx] = H.u;
    }
}

// ---------------- gates via HMMA: [MROWS x 32] = xnh @ Wg^T, sigmoid fused ----------------
// tile 128x32, K=1024, 4-stage cp.async (A 16KB + B 4KB per stage), 8 warps (4M x 2N).
__device__ __forceinline__ void gates_load_stage(const __half* Ag, const __half* Bg,
                                                 uint32_t stage_base, int tid, int kit) {
    const __half* Ak = Ag + kit * BK;
    const __half* Bk = Bg + kit * BK;
    uint32_t sa = stage_base;
    uint32_t sbb = stage_base + 16384;
#pragma unroll
    for (int i = 0; i < 4; i++) {
        int u = tid + i * 256;          // 0..1023
        int row = u >> 3, c = u & 7;
        uint32_t off = swz((uint32_t)(row * 128 + c * 16));
        cp_async16(sa + off, Ak + (size_t)row * KTOT + c * 8);
    }
    {
        int row = tid >> 3, c = tid & 7;  // 32 rows x 8 chunks = 256
        uint32_t off = swz((uint32_t)(row * 128 + c * 16));
        cp_async16(sbb + off, Bk + (size_t)row * KTOT + c * 8);
    }
}

__global__ __launch_bounds__(256) void gates_mma_kernel(
    const __half* __restrict__ A, const __half* __restrict__ Wgh,
    const float* __restrict__ bg, const float* __restrict__ eig,
    float* __restrict__ a_out, float* __restrict__ beta_out)
{
    extern __shared__ char smem[];
    const uint32_t sb = smem_u32(smem);
    const int tid = threadIdx.x, wid = tid >> 5, lane = tid & 31;
    const int m0 = blockIdx.x * 128;
    const int warpM = (wid & 3) * 32;
    const int warpN = (wid >> 2) * 16;

    const __half* Ag = A + (size_t)m0 * KTOT;

    float acc[2][2][4];
#pragma unroll
    for (int mi = 0; mi < 2; mi++)
#pragma unroll
        for (int ni = 0; ni < 2; ni++)
#pragma unroll
            for (int q = 0; q < 4; q++) acc[mi][ni][q] = 0.f;

    const int arow = warpM + (lane & 15);
    const int brow = warpN + (lane & 7) + ((lane >> 4) << 3);
    const uint32_t acol_base = (uint32_t)((lane >> 4) << 4);
    const uint32_t bcol_base = (uint32_t)(((lane >> 3) & 1) << 4);

#pragma unroll
    for (int s = 0; s < NSTG - 1; s++) { gates_load_stage(Ag, Wgh, sb + s * GATES_STG, tid, s); CP_COMMIT(); }

    for (int it = 0; it < KI; it++) {
        if (it + NSTG - 1 < KI)
            gates_load_stage(Ag, Wgh, sb + ((it + NSTG - 1) & 3) * GATES_STG, tid, it + NSTG - 1);
        CP_COMMIT();
        CP_WAIT(NSTG - 1);
        __syncthreads();

        const uint32_t sa  = sb + (it & 3) * GATES_STG;
        const uint32_t sbb = sa + 16384;
#pragma unroll
        for (int kk = 0; kk < 4; kk++) {
            const uint32_t kByte = (uint32_t)(kk * 32);
            uint32_t a[2][4];
#pragma unroll
            for (int mi = 0; mi < 2; mi++) {
                uint32_t off = swz((uint32_t)((arow + mi * 16) * 128) + kByte + acol_base);
                ldsm_x4(a[mi][0], a[mi][1], a[mi][2], a[mi][3], sa + off);
            }
            uint32_t b0, b1, b2, b3;
            {
                uint32_t off = swz((uint32_t)(brow * 128) + kByte + bcol_base);
                ldsm_x4(b0, b1, b2, b3, sbb + off);
            }
#pragma unroll
            for (int mi = 0; mi < 2; mi++) {
                mma16816(acc[mi][0][0], acc[mi][0][1], acc[mi][0][2], acc[mi][0][3],
                         a[mi][0], a[mi][1], a[mi][2], a[mi][3], b0, b1);
                mma16816(acc[mi][1][0], acc[mi][1][1], acc[mi][1][2], acc[mi][1][3],
                         a[mi][0], a[mi][1], a[mi][2], a[mi][3], b2, b3);
            }
        }
        __syncthreads();
    }

    // epilogue: bias + sigmoid; g<16 -> a_out (x tanh(eig)), else beta_out
    const int crow = m0 + warpM + (lane >> 2);
    const int ccol0 = warpN + 2 * (lane & 3);
#pragma unroll
    for (int mi = 0; mi < 2; mi++)
#pragma unroll
        for (int ni = 0; ni < 2; ni++) {
            int g0 = ccol0 + ni * 8;
#pragma unroll
            for (int q = 0; q < 4; q++) {
                int g = g0 + (q & 1);
                int row = crow + mi * 16 + ((q >> 1) << 3);
                float sg = 1.f / (1.f + expf(-(acc[mi][ni][q] + bg[g])));
                if (g < 16) a_out[(size_t)row * NHEAD + g] = tanhf(eig[g]) * sg;
                else        beta_out[(size_t)row * NHEAD + (g - 16)] = sg;
            }
        }
}

// ---------------- scan pass 1: per-chunk contribution with reference masking ----------------
__global__ __launch_bounds__(64) void scan1_kernel(
    const float* __restrict__ a_buf, const float* __restrict__ beta_buf,
    const float* __restrict__ xn,
    float* __restrict__ contrib, float* __restrict__ cum_out,
    float* __restrict__ Cc, float* __restrict__ Ee)
{
    const int blk = blockIdx.x;
    const int h   = blk & 15;
    const int bn  = blk >> 4;
    const int base_pos = bn * CSZ;
    const int d = threadIdx.x;

    __shared__ float s_a[CSZ], s_cum[CSZ], s_inv[CSZ], s_beta[CSZ];
    if (d < CSZ) {
        s_a[d]    = a_buf[(size_t)(base_pos + d) * NHEAD + h];
        s_beta[d] = beta_buf[(size_t)(base_pos + d) * NHEAD + h];
    }
    __syncthreads();
    if (d == 0) {
        float c = 1.f;
#pragma unroll
        for (int j = 0; j < CSZ; j++) {
            float cp = c;
            c = c * s_a[j];
            s_cum[j] = c;
            s_inv[j] = (fabsf(cp) > 1e-8f) ? (1.f / cp) : 0.f;
        }
    }
    __syncthreads();
    if (d < CSZ) cum_out[(size_t)(base_pos + d) * NHEAD + h] = s_cum[d];

    float Q = 0.f, hc = 0.f;
#pragma unroll
    for (int j = 0; j < CSZ; j++) {
        size_t idx = (size_t)(base_pos + j) * HID + h * HD + d;
        float bv = s_beta[j] * xn[idx];
        hc = fmaf(s_cum[j], Q, bv);
        contrib[idx] = hc;
        Q = fmaf(bv, s_inv[j], Q);
    }
    Ee[(size_t)bn * HID + h * HD + d] = hc;
    if (d == 0) Cc[(size_t)bn * NHEAD + h] = s_cum[CSZ - 1];
}

// ---------------- scan pass 2: 3-phase group scan over 256 chunks ----------------
__global__ __launch_bounds__(256) void scan2a_kernel(
    const float* __restrict__ Cc, const float* __restrict__ Ee,
    float* __restrict__ P2, float* __restrict__ E2)
{
    int idx = blockIdx.x * 256 + threadIdx.x;   // 65536
    int ch = idx & 4095, grp = idx >> 12;
    int b = ch >> 10, c = ch & 1023, h = c >> 6;
    float P = 1.f, E = 0.f;
#pragma unroll
    for (int i = 0; i < 16; i++) {
        int bn = b * NCHUNK + grp * 16 + i;
        float cc = Cc[(size_t)bn * NHEAD + h];
        E = fmaf(cc, E, Ee[(size_t)bn * HID + c]);
        P *= cc;
    }
    P2[idx] = P; E2[idx] = E;
}
__global__ __launch_bounds__(128) void scan2b_kernel(
    const float* __restrict__ P2, const float* __restrict__ E2, float* __restrict__ G2)
{
    int ch = blockIdx.x * 128 + threadIdx.x;    // 4096
    float car = 0.f;
#pragma unroll
    for (int g = 0; g < 16; g++) {
        G2[g * 4096 + ch] = car;
        car = fmaf(P2[g * 4096 + ch], car, E2[g * 4096 + ch]);
    }
}
__global__ __launch_bounds__(256) void scan2c_kernel(
    const float* __restrict__ Cc, const float* __restrict__ Ee,
    const float* __restrict__ G2, float* __restrict__ carry)
{
    int idx = blockIdx.x * 256 + threadIdx.x;
    int ch = idx & 4095, grp = idx >> 12;
    int b = ch >> 10, c = ch & 1023, h = c >> 6;
    float car = G2[grp * 4096 + ch];
#pragma unroll
    for (int i = 0; i < 16; i++) {
        int bn = b * NCHUNK + grp * 16 + i;
        carry[(size_t)bn * HID + c] = car;
        car = fmaf(Cc[(size_t)bn * NHEAD + h], car, Ee[(size_t)bn * HID + c]);
    }
}

// ---------------- scan pass 3: h = cum*carry + contrib -> fp16 + h_final ----------------
__global__ __launch_bounds__(256) void scan3_kernel(
    const float* __restrict__ cum, const float* __restrict__ carry,
    const float* __restrict__ contrib,
    __half* __restrict__ Abuf, float* __restrict__ h_final)
{
    int g = blockIdx.x * 256 + threadIdx.x;     // float4 index
    int pos = g >> 8;
    int c0  = (g & 255) << 2;
    int h   = c0 >> 6;
    int bn  = pos >> 4;

    float cm = cum[(size_t)pos * NHEAD + h];
    float4 cr = reinterpret_cast<const float4*>(carry + (size_t)bn * HID)[c0 >> 2];
    float4 hv = reinterpret_cast<const float4*>(contrib)[g];
    hv.x = fmaf(cm, cr.x, hv.x);
    hv.y = fmaf(cm, cr.y, hv.y);
    hv.z = fmaf(cm, cr.z, hv.z);
    hv.w = fmaf(cm, cr.w, hv.w);

    union { __half h[4]; uint2 u; } H;
    H.h[0] = __float2half_rn(hv.x);
    H.h[1] = __float2half_rn(hv.y);
    H.h[2] = __float2half_rn(hv.z);
    H.h[3] = __float2half_rn(hv.w);
    reinterpret_cast<uint2*>(Abuf)[g] = H.u;

    if ((pos & (SEQ - 1)) == SEQ - 1) {
        int b = pos >> 12;
        reinterpret_cast<float4*>(h_final + (size_t)b * HID)[c0 >> 2] = hv;
    }
}

// ---------------- launch ----------------
extern "C" void kernel_launch(void* const* d_in, const int* in_sizes, int n_in,
                              void* d_out, int out_size)
{
    const float* x       = (const float*)d_in[0];
    const float* W_in    = (const float*)d_in[1];
    const float* ln_g    = (const float*)d_in[2];
    const float* ln_b    = (const float*)d_in[3];
    const float* W_gate  = (const float*)d_in[4];
    const float* b_gate  = (const float*)d_in[5];
    const float* eig_raw = (const float*)d_in[6];
    const float* W_out   = (const float*)d_in[7];

    float* out     = (float*)d_out;
    float* h_final = out + (size_t)MROWS * HID;

    __half *Abuf, *Bbuf;
    float *xp, *xn, *contrib, *ab, *bb, *cum, *Cc, *Ee, *carry, *P2, *E2, *G2;
    cudaGetSymbolAddress((void**)&Abuf,    g_Abuf);
    cudaGetSymbolAddress((void**)&Bbuf,    g_Bbuf);
    cudaGetSymbolAddress((void**)&xp,      g_xp);
    cudaGetSymbolAddress((void**)&xn,      g_xn);
    cudaGetSymbolAddress((void**)&contrib, g_contrib);
    cudaGetSymbolAddress((void**)&ab,      g_a);
    cudaGetSymbolAddress((void**)&bb,      g_beta);
    cudaGetSymbolAddress((void**)&cum,     g_cum);
    cudaGetSymbolAddress((void**)&Cc,      g_C);
    cudaGetSymbolAddress((void**)&Ee,      g_E);
    cudaGetSymbolAddress((void**)&carry,   g_carry);
    cudaGetSymbolAddress((void**)&P2,      g_P2);
    cudaGetSymbolAddress((void**)&E2,      g_E2);
    cudaGetSymbolAddress((void**)&G2,      g_G2);

    cudaFuncSetAttribute(mma_gemm_kernel,  cudaFuncAttributeMaxDynamicSharedMemorySize, GEMM_SMEM);
    cudaFuncSetAttribute(gates_mma_kernel, cudaFuncAttributeMaxDynamicSharedMemorySize, GATES_SMEM);

    // 1) convert x and W_in to fp16, GEMM1 -> xp
    convert_half_kernel<<<(MROWS * HID / 4) / 256, 256>>>(x, Abuf);
    convert_half_kernel<<<(HID * HID / 4) / 256, 256>>>(W_in, Bbuf);
    mma_gemm_kernel<<<dim3(HID / 128, MROWS / 128), 256, GEMM_SMEM>>>(Abuf, Bbuf, xp);

    // 2) LN -> xn (fp32) + xnh (fp16, reuses Abuf); gates via HMMA
    ln_kernel<<<MROWS / 8, 256>>>(xp, ln_g, ln_b, xn, Abuf);
    convert_half_kernel<<<(2 * NHEAD * HID / 4) / 256, 256>>>(W_gate, Bbuf);
    gates_mma_kernel<<<MROWS / 128, 256, GATES_SMEM>>>(Abuf, Bbuf, b_gate, eig_raw, ab, bb);

    // 3) chunked scan (reference masking) -> fp16 h_all (Abuf) + h_final
    scan1_kernel<<<BNCH * NHEAD, 64>>>(ab, bb, xn, contrib, cum, Cc, Ee);
    scan2a_kernel<<<(BATCH * HID * 16) / 256, 256>>>(Cc, Ee, P2, E2);
    scan2b_kernel<<<(BATCH * HID) / 128, 128>>>(P2, E2, G2);
    scan2c_kernel<<<(BATCH * HID * 16) / 256, 256>>>(Cc, Ee, G2, carry);
    scan3_kernel<<<MROWS, 256>>>(cum, carry, contrib, Abuf, h_final);

    // 4) GEMM2 -> out
    convert_half_kernel<<<(HID * HID / 4) / 256, 256>>>(W_out, Bbuf);
    mma_gemm_kernel<<<dim3(HID / 128, MROWS / 128), 256, GEMM_SMEM>>>(Abuf, Bbuf, out);
}

// round 7
// speedup vs baseline: 2.9844x; 1.1814x over previous
#include <cuda_runtime.h>
#include <cuda_fp16.h>
#include <math.h>
#include <stdint.h>

// ---------------- problem constants ----------------
#define BATCH   4
#define SEQ     4096
#define HID     1024
#define NHEAD   16
#define HD      64
#define CSZ     16
#define MROWS   (BATCH*SEQ)        // 16384
#define NCHUNK  (SEQ/CSZ)          // 256
#define BNCH    (BATCH*NCHUNK)     // 1024
#define KTOT    1024               // single fp16 pass
#define BK      64                 // fp16 K per stage (128 bytes/row)
#define KI      (KTOT/BK)          // 16
#define NSTG    3                  // big-GEMM stages (96KB -> 2 CTAs/SM)
#define STG_BYTES 32768            // A 16KB + B 16KB
#define GEMM_SMEM (NSTG*STG_BYTES) // 96 KB
#define GNSTG   4                  // gates stages
#define GATES_STG 20480            // A 16KB + B 4KB
#define GATES_SMEM (GNSTG*GATES_STG)// 80 KB

// ---------------- scratch (static device globals) ----------------
__device__ __align__(16) __half g_Abuf[(size_t)MROWS*KTOT]; // 32 MB (x fp16 -> xn fp16 -> h fp16)
__device__ __align__(16) __half g_Bbuf[(size_t)HID*KTOT];   // 2 MB
__device__ __align__(16) __half g_xph[(size_t)MROWS*HID];   // 32 MB fp16 xp
__device__ float g_contrib[MROWS*HID];
__device__ float g_a[MROWS*NHEAD];
__device__ float g_beta[MROWS*NHEAD];
__device__ float g_cum[MROWS*NHEAD];
__device__ float g_C[BNCH*NHEAD];
__device__ float g_E[BNCH*HID];
__device__ float g_carry[BNCH*HID];
__device__ float g_P2[BATCH*HID*16];
__device__ float g_E2[BATCH*HID*16];
__device__ float g_G2[BATCH*HID*16];

// ---------------- PTX helpers (sm_80-level: compile-safe on compute_103) ----------------
__device__ __forceinline__ uint32_t smem_u32(const void* p) {
    uint32_t a;
    asm("{ .reg .u64 t; cvta.to.shared.u64 t, %1; cvt.u32.u64 %0, t; }" : "=r"(a) : "l"(p));
    return a;
}
#define CP_COMMIT() asm volatile("cp.async.commit_group;" ::: "memory")
#define CP_WAIT(N)  asm volatile("cp.async.wait_group %0;" :: "n"(N) : "memory")
__device__ __forceinline__ void cp_async16(uint32_t s, const void* g) {
    asm volatile("cp.async.cg.shared.global [%0], [%1], 16;" :: "r"(s), "l"(g) : "memory");
}
__device__ __forceinline__ void ldsm_x4(uint32_t& r0, uint32_t& r1, uint32_t& r2, uint32_t& r3, uint32_t addr) {
    asm volatile("ldmatrix.sync.aligned.m8n8.x4.shared.b16 {%0,%1,%2,%3}, [%4];"
                 : "=r"(r0), "=r"(r1), "=r"(r2), "=r"(r3) : "r"(addr));
}
__device__ __forceinline__ void mma16816(float& c0, float& c1, float& c2, float& c3,
                                         uint32_t a0, uint32_t a1, uint32_t a2, uint32_t a3,
                                         uint32_t b0, uint32_t b1) {
    asm volatile("mma.sync.aligned.m16n8k16.row.col.f32.f16.f16.f32 "
                 "{%0,%1,%2,%3}, {%4,%5,%6,%7}, {%8,%9}, {%0,%1,%2,%3};"
                 : "+f"(c0), "+f"(c1), "+f"(c2), "+f"(c3)
                 : "r"(a0), "r"(a1), "r"(a2), "r"(a3), "r"(b0), "r"(b1));
}
__device__ __forceinline__ uint32_t swz(uint32_t off) { return off ^ ((off >> 3) & 0x70); }

// ---------------- fp32 -> fp16 conversion (plain) ----------------
__global__ __launch_bounds__(256) void convert_half_kernel(
    const float* __restrict__ in, __half* __restrict__ out)
{
    int g = blockIdx.x * 256 + threadIdx.x;
    float4 v = reinterpret_cast<const float4*>(in)[g];
    union { __half h[4]; uint2 u; } H;
    H.h[0] = __float2half_rn(v.x);
    H.h[1] = __float2half_rn(v.y);
    H.h[2] = __float2half_rn(v.z);
    H.h[3] = __float2half_rn(v.w);
    reinterpret_cast<uint2*>(out)[g] = H.u;
}

// ---------------- mma.sync fp16 GEMM: C[m,n] = sum_k A[m,k]*B[n,k], K=1024 ----------------
// 128x128 tile, BK=64, 3-stage cp.async, 256 threads (8 warps, 32x64 each), 2 CTAs/SM.
__device__ __forceinline__ void load_stage(const __half* Ag, const __half* Bg,
                                           uint32_t stage_base, int tid, int kit) {
    const __half* Ak = Ag + kit * BK;
    const __half* Bk = Bg + kit * BK;
    uint32_t sa = stage_base;
    uint32_t sbb = stage_base + 16384;
#pragma unroll
    for (int i = 0; i < 4; i++) {
        int u = tid + i * 256;
        int row = u >> 3, c = u & 7;
        uint32_t off = swz((uint32_t)(row * 128 + c * 16));
        cp_async16(sa  + off, Ak + (size_t)row * KTOT + c * 8);
        cp_async16(sbb + off, Bk + (size_t)row * KTOT + c * 8);
    }
}

template<bool HALF_OUT>
__global__ __launch_bounds__(256, 2) void mma_gemm_kernel(
    const __half* __restrict__ A, const __half* __restrict__ B,
    float* __restrict__ C, __half* __restrict__ Ch)
{
    extern __shared__ char smem[];
    const uint32_t sb = smem_u32(smem);
    const int tid = threadIdx.x, wid = tid >> 5, lane = tid & 31;
    const int m0 = blockIdx.y * 128;
    const int n0 = blockIdx.x * 128;
    const int warpM = (wid & 3) * 32;
    const int warpN = (wid >> 2) * 64;

    const __half* Ag = A + (size_t)m0 * KTOT;
    const __half* Bg = B + (size_t)n0 * KTOT;

    float acc[2][8][4];
#pragma unroll
    for (int mi = 0; mi < 2; mi++)
#pragma unroll
        for (int ni = 0; ni < 8; ni++)
#pragma unroll
            for (int q = 0; q < 4; q++) acc[mi][ni][q] = 0.f;

    const int arow = warpM + (lane & 15);
    const int brow = warpN + (lane & 7) + ((lane >> 4) << 3);
    const uint32_t acol_base = (uint32_t)((lane >> 4) << 4);
    const uint32_t bcol_base = (uint32_t)(((lane >> 3) & 1) << 4);

#pragma unroll
    for (int s = 0; s < NSTG - 1; s++) { load_stage(Ag, Bg, sb + s * STG_BYTES, tid, s); CP_COMMIT(); }

    for (int it = 0; it < KI; it++) {
        if (it + NSTG - 1 < KI)
            load_stage(Ag, Bg, sb + ((it + NSTG - 1) % NSTG) * STG_BYTES, tid, it + NSTG - 1);
        CP_COMMIT();
        CP_WAIT(NSTG - 1);
        __syncthreads();

        const uint32_t sa  = sb + (it % NSTG) * STG_BYTES;
        const uint32_t sbb = sa + 16384;
#pragma unroll
        for (int kk = 0; kk < 4; kk++) {
            const uint32_t kByte = (uint32_t)(kk * 32);
            uint32_t a[2][4];
#pragma unroll
            for (int mi = 0; mi < 2; mi++) {
                uint32_t off = swz((uint32_t)((arow + mi * 16) * 128) + kByte + acol_base);
                ldsm_x4(a[mi][0], a[mi][1], a[mi][2], a[mi][3], sa + off);
            }
            uint32_t b[8][2];
#pragma unroll
            for (int nb = 0; nb < 4; nb++) {
                uint32_t off = swz((uint32_t)((brow + nb * 16) * 128) + kByte + bcol_base);
                uint32_t r0, r1, r2, r3;
                ldsm_x4(r0, r1, r2, r3, sbb + off);
                b[nb * 2][0] = r0; b[nb * 2][1] = r1;
                b[nb * 2 + 1][0] = r2; b[nb * 2 + 1][1] = r3;
            }
#pragma unroll
            for (int mi = 0; mi < 2; mi++)
#pragma unroll
                for (int ni = 0; ni < 8; ni++)
                    mma16816(acc[mi][ni][0], acc[mi][ni][1], acc[mi][ni][2], acc[mi][ni][3],
                             a[mi][0], a[mi][1], a[mi][2], a[mi][3], b[ni][0], b[ni][1]);
        }
        __syncthreads();
    }

    const int crow = m0 + warpM + (lane >> 2);
    const int ccol = n0 + warpN + 2 * (lane & 3);
#pragma unroll
    for (int mi = 0; mi < 2; mi++)
#pragma unroll
        for (int ni = 0; ni < 8; ni++) {
            if (HALF_OUT) {
                __half* p0 = Ch + (size_t)(crow + mi * 16) * HID + ccol + ni * 8;
                __half* p1 = p0 + 8 * HID;
                *reinterpret_cast<__half2*>(p0) = __floats2half2_rn(acc[mi][ni][0], acc[mi][ni][1]);
                *reinterpret_cast<__half2*>(p1) = __floats2half2_rn(acc[mi][ni][2], acc[mi][ni][3]);
            } else {
                float* p0 = C + (size_t)(crow + mi * 16) * HID + ccol + ni * 8;
                float* p1 = p0 + 8 * HID;
                *reinterpret_cast<float2*>(p0) = make_float2(acc[mi][ni][0], acc[mi][ni][1]);
                *reinterpret_cast<float2*>(p1) = make_float2(acc[mi][ni][2], acc[mi][ni][3]);
            }
        }
}

// ---------------- LayerNorm (warp per row), fp16 in -> fp16 out ----------------
__global__ __launch_bounds__(256) void ln_kernel(
    const __half* __restrict__ xph, const float* __restrict__ ln_g,
    const float* __restrict__ ln_b, __half* __restrict__ xnh)
{
    int w = threadIdx.x >> 5, lane = threadIdx.x & 31;
    int row = blockIdx.x * 8 + w;
    const uint2* xr = reinterpret_cast<const uint2*>(xph + (size_t)row * HID);
    float v[8][4];
    float s = 0.f, s2 = 0.f;
#pragma unroll
    for (int i = 0; i < 8; i++) {
        union { uint2 u; __half h[4]; } U;
        U.u = xr[lane + 32 * i];
#pragma unroll
        for (int q = 0; q < 4; q++) {
            float f = __half2float(U.h[q]);
            v[i][q] = f;
            s += f; s2 += f * f;
        }
    }
#pragma unroll
    for (int o = 16; o > 0; o >>= 1) {
        s  += __shfl_xor_sync(0xffffffffu, s, o);
        s2 += __shfl_xor_sync(0xffffffffu, s2, o);
    }
    float mu = s * (1.f / HID);
    float rs = rsqrtf(s2 * (1.f / HID) - mu * mu + 1e-5f);
    uint2* xh = reinterpret_cast<uint2*>(xnh + (size_t)row * HID);
#pragma unroll
    for (int i = 0; i < 8; i++) {
        int idx = lane + 32 * i;
        float4 g4 = reinterpret_cast<const float4*>(ln_g)[idx];
        float4 b4 = reinterpret_cast<const float4*>(ln_b)[idx];
        union { uint2 u; __half2 h2[2]; } H;
        H.h2[0] = __floats2half2_rn((v[i][0] - mu) * rs * g4.x + b4.x,
                                    (v[i][1] - mu) * rs * g4.y + b4.y);
        H.h2[1] = __floats2half2_rn((v[i][2] - mu) * rs * g4.z + b4.z,
                                    (v[i][3] - mu) * rs * g4.w + b4.w);
        xh[idx] = H.u;
    }
}

// ---------------- gates via HMMA: [MROWS x 32] = xnh @ Wg^T, sigmoid fused ----------------
__device__ __forceinline__ void gates_load_stage(const __half* Ag, const __half* Bg,
                                                 uint32_t stage_base, int tid, int kit) {
    const __half* Ak = Ag + kit * BK;
    const __half* Bk = Bg + kit * BK;
    uint32_t sa = stage_base;
    uint32_t sbb = stage_base + 16384;
#pragma unroll
    for (int i = 0; i < 4; i++) {
        int u = tid + i * 256;
        int row = u >> 3, c = u & 7;
        uint32_t off = swz((uint32_t)(row * 128 + c * 16));
        cp_async16(sa + off, Ak + (size_t)row * KTOT + c * 8);
    }
    {
        int row = tid >> 3, c = tid & 7;
        uint32_t off = swz((uint32_t)(row * 128 + c * 16));
        cp_async16(sbb + off, Bk + (size_t)row * KTOT + c * 8);
    }
}

__global__ __launch_bounds__(256) void gates_mma_kernel(
    const __half* __restrict__ A, const __half* __restrict__ Wgh,
    const float* __restrict__ bg, const float* __restrict__ eig,
    float* __restrict__ a_out, float* __restrict__ beta_out)
{
    extern __shared__ char smem[];
    const uint32_t sb = smem_u32(smem);
    const int tid = threadIdx.x, wid = tid >> 5, lane = tid & 31;
    const int m0 = blockIdx.x * 128;
    const int warpM = (wid & 3) * 32;
    const int warpN = (wid >> 2) * 16;

    const __half* Ag = A + (size_t)m0 * KTOT;

    float acc[2][2][4];
#pragma unroll
    for (int mi = 0; mi < 2; mi++)
#pragma unroll
        for (int ni = 0; ni < 2; ni++)
#pragma unroll
            for (int q = 0; q < 4; q++) acc[mi][ni][q] = 0.f;

    const int arow = warpM + (lane & 15);
    const int brow = warpN + (lane & 7) + ((lane >> 4) << 3);
    const uint32_t acol_base = (uint32_t)((lane >> 4) << 4);
    const uint32_t bcol_base = (uint32_t)(((lane >> 3) & 1) << 4);

#pragma unroll
    for (int s = 0; s < GNSTG - 1; s++) { gates_load_stage(Ag, Wgh, sb + s * GATES_STG, tid, s); CP_COMMIT(); }

    for (int it = 0; it < KI; it++) {
        if (it + GNSTG - 1 < KI)
            gates_load_stage(Ag, Wgh, sb + ((it + GNSTG - 1) & 3) * GATES_STG, tid, it + GNSTG - 1);
        CP_COMMIT();
        CP_WAIT(GNSTG - 1);
        __syncthreads();

        const uint32_t sa  = sb + (it & 3) * GATES_STG;
        const uint32_t sbb = sa + 16384;
#pragma unroll
        for (int kk = 0; kk < 4; kk++) {
            const uint32_t kByte = (uint32_t)(kk * 32);
            uint32_t a[2][4];
#pragma unroll
            for (int mi = 0; mi < 2; mi++) {
                uint32_t off = swz((uint32_t)((arow + mi * 16) * 128) + kByte + acol_base);
                ldsm_x4(a[mi][0], a[mi][1], a[mi][2], a[mi][3], sa + off);
            }
            uint32_t b0, b1, b2, b3;
            {
                uint32_t off = swz((uint32_t)(brow * 128) + kByte + bcol_base);
                ldsm_x4(b0, b1, b2, b3, sbb + off);
            }
#pragma unroll
            for (int mi = 0; mi < 2; mi++) {
                mma16816(acc[mi][0][0], acc[mi][0][1], acc[mi][0][2], acc[mi][0][3],
                         a[mi][0], a[mi][1], a[mi][2], a[mi][3], b0, b1);
                mma16816(acc[mi][1][0], acc[mi][1][1], acc[mi][1][2], acc[mi][1][3],
                         a[mi][0], a[mi][1], a[mi][2], a[mi][3], b2, b3);
            }
        }
        __syncthreads();
    }

    const int crow = m0 + warpM + (lane >> 2);
    const int ccol0 = warpN + 2 * (lane & 3);
#pragma unroll
    for (int mi = 0; mi < 2; mi++)
#pragma unroll
        for (int ni = 0; ni < 2; ni++) {
            int g0 = ccol0 + ni * 8;
#pragma unroll
            for (int q = 0; q < 4; q++) {
                int g = g0 + (q & 1);
                int row = crow + mi * 16 + ((q >> 1) << 3);
                float sg = 1.f / (1.f + expf(-(acc[mi][ni][q] + bg[g])));
                if (g < 16) a_out[(size_t)row * NHEAD + g] = tanhf(eig[g]) * sg;
                else        beta_out[(size_t)row * NHEAD + (g - 16)] = sg;
            }
        }
}

// ---------------- scan pass 1: per-chunk contribution with reference masking ----------------
__global__ __launch_bounds__(64) void scan1_kernel(
    const float* __restrict__ a_buf, const float* __restrict__ beta_buf,
    const __half* __restrict__ xnh,
    float* __restrict__ contrib, float* __restrict__ cum_out,
    float* __restrict__ Cc, float* __restrict__ Ee)
{
    const int blk = blockIdx.x;
    const int h   = blk & 15;
    const int bn  = blk >> 4;
    const int base_pos = bn * CSZ;
    const int d = threadIdx.x;

    __shared__ float s_a[CSZ], s_cum[CSZ], s_inv[CSZ], s_beta[CSZ];
    if (d < CSZ) {
        s_a[d]    = a_buf[(size_t)(base_pos + d) * NHEAD + h];
        s_beta[d] = beta_buf[(size_t)(base_pos + d) * NHEAD + h];
    }
    __syncthreads();
    if (d == 0) {
        float c = 1.f;
#pragma unroll
        for (int j = 0; j < CSZ; j++) {
            float cp = c;
            c = c * s_a[j];
            s_cum[j] = c;
            s_inv[j] = (fabsf(cp) > 1e-8f) ? (1.f / cp) : 0.f;
        }
    }
    __syncthreads();
    if (d < CSZ) cum_out[(size_t)(base_pos + d) * NHEAD + h] = s_cum[d];

    float Q = 0.f, hc = 0.f;
#pragma unroll
    for (int j = 0; j < CSZ; j++) {
        size_t idx = (size_t)(base_pos + j) * HID + h * HD + d;
        float bv = s_beta[j] * __half2float(xnh[idx]);
        hc = fmaf(s_cum[j], Q, bv);
        contrib[idx] = hc;
        Q = fmaf(bv, s_inv[j], Q);
    }
    Ee[(size_t)bn * HID + h * HD + d] = hc;
    if (d == 0) Cc[(size_t)bn * NHEAD + h] = s_cum[CSZ - 1];
}

// ---------------- scan pass 2: 3-phase group scan over 256 chunks ----------------
__global__ __launch_bounds__(256) void scan2a_kernel(
    const float* __restrict__ Cc, const float* __restrict__ Ee,
    float* __restrict__ P2, float* __restrict__ E2)
{
    int idx = blockIdx.x * 256 + threadIdx.x;
    int ch = idx & 4095, grp = idx >> 12;
    int b = ch >> 10, c = ch & 1023, h = c >> 6;
    float P = 1.f, E = 0.f;
#pragma unroll
    for (int i = 0; i < 16; i++) {
        int bn = b * NCHUNK + grp * 16 + i;
        float cc = Cc[(size_t)bn * NHEAD + h];
        E = fmaf(cc, E, Ee[(size_t)bn * HID + c]);
        P *= cc;
    }
    P2[idx] = P; E2[idx] = E;
}
__global__ __launch_bounds__(128) void scan2b_kernel(
    const float* __restrict__ P2, const float* __restrict__ E2, float* __restrict__ G2)
{
    int ch = blockIdx.x * 128 + threadIdx.x;
    float car = 0.f;
#pragma unroll
    for (int g = 0; g < 16; g++) {
        G2[g * 4096 + ch] = car;
        car = fmaf(P2[g * 4096 + ch], car, E2[g * 4096 + ch]);
    }
}
__global__ __launch_bounds__(256) void scan2c_kernel(
    const float* __restrict__ Cc, const float* __restrict__ Ee,
    const float* __restrict__ G2, float* __restrict__ carry)
{
    int idx = blockIdx.x * 256 + threadIdx.x;
    int ch = idx & 4095, grp = idx >> 12;
    int b = ch >> 10, c = ch & 1023, h = c >> 6;
    float car = G2[grp * 4096 + ch];
#pragma unroll
    for (int i = 0; i < 16; i++) {
        int bn = b * NCHUNK + grp * 16 + i;
        carry[(size_t)bn * HID + c] = car;
        car = fmaf(Cc[(size_t)bn * NHEAD + h], car, Ee[(size_t)bn * HID + c]);
    }
}

// ---------------- scan pass 3: h = cum*carry + contrib -> fp16 + h_final ----------------
__global__ __launch_bounds__(256) void scan3_kernel(
    const float* __restrict__ cum, const float* __restrict__ carry,
    const float* __restrict__ contrib,
    __half* __restrict__ Abuf, float* __restrict__ h_final)
{
    int g = blockIdx.x * 256 + threadIdx.x;
    int pos = g >> 8;
    int c0  = (g & 255) << 2;
    int h   = c0 >> 6;
    int bn  = pos >> 4;

    float cm = cum[(size_t)pos * NHEAD + h];
    float4 cr = reinterpret_cast<const float4*>(carry + (size_t)bn * HID)[c0 >> 2];
    float4 hv = reinterpret_cast<const float4*>(contrib)[g];
    hv.x = fmaf(cm, cr.x, hv.x);
    hv.y = fmaf(cm, cr.y, hv.y);
    hv.z = fmaf(cm, cr.z, hv.z);
    hv.w = fmaf(cm, cr.w, hv.w);

    union { __half h[4]; uint2 u; } H;
    H.h[0] = __float2half_rn(hv.x);
    H.h[1] = __float2half_rn(hv.y);
    H.h[2] = __float2half_rn(hv.z);
    H.h[3] = __float2half_rn(hv.w);
    reinterpret_cast<uint2*>(Abuf)[g] = H.u;

    if ((pos & (SEQ - 1)) == SEQ - 1) {
        int b = pos >> 12;
        reinterpret_cast<float4*>(h_final + (size_t)b * HID)[c0 >> 2] = hv;
    }
}

// ---------------- launch ----------------
extern "C" void kernel_launch(void* const* d_in, const int* in_sizes, int n_in,
                              void* d_out, int out_size)
{
    const float* x       = (const float*)d_in[0];
    const float* W_in    = (const float*)d_in[1];
    const float* ln_g    = (const float*)d_in[2];
    const float* ln_b    = (const float*)d_in[3];
    const float* W_gate  = (const float*)d_in[4];
    const float* b_gate  = (const float*)d_in[5];
    const float* eig_raw = (const float*)d_in[6];
    const float* W_out   = (const float*)d_in[7];

    float* out     = (float*)d_out;
    float* h_final = out + (size_t)MROWS * HID;

    __half *Abuf, *Bbuf, *xph;
    float *contrib, *ab, *bb, *cum, *Cc, *Ee, *carry, *P2, *E2, *G2;
    cudaGetSymbolAddress((void**)&Abuf,    g_Abuf);
    cudaGetSymbolAddress((void**)&Bbuf,    g_Bbuf);
    cudaGetSymbolAddress((void**)&xph,     g_xph);
    cudaGetSymbolAddress((void**)&contrib, g_contrib);
    cudaGetSymbolAddress((void**)&ab,      g_a);
    cudaGetSymbolAddress((void**)&bb,      g_beta);
    cudaGetSymbolAddress((void**)&cum,     g_cum);
    cudaGetSymbolAddress((void**)&Cc,      g_C);
    cudaGetSymbolAddress((void**)&Ee,      g_E);
    cudaGetSymbolAddress((void**)&carry,   g_carry);
    cudaGetSymbolAddress((void**)&P2,      g_P2);
    cudaGetSymbolAddress((void**)&E2,      g_E2);
    cudaGetSymbolAddress((void**)&G2,      g_G2);

    cudaFuncSetAttribute(mma_gemm_kernel<true>,  cudaFuncAttributeMaxDynamicSharedMemorySize, GEMM_SMEM);
    cudaFuncSetAttribute(mma_gemm_kernel<false>, cudaFuncAttributeMaxDynamicSharedMemorySize, GEMM_SMEM);
    cudaFuncSetAttribute(gates_mma_kernel, cudaFuncAttributeMaxDynamicSharedMemorySize, GATES_SMEM);

    // 1) convert x and W_in to fp16, GEMM1 -> xph (fp16)
    convert_half_kernel<<<(MROWS * HID / 4) / 256, 256>>>(x, Abuf);
    convert_half_kernel<<<(HID * HID / 4) / 256, 256>>>(W_in, Bbuf);
    mma_gemm_kernel<true><<<dim3(HID / 128, MROWS / 128), 256, GEMM_SMEM>>>(Abuf, Bbuf, nullptr, xph);

    // 2) LN (fp16 -> fp16 xnh in Abuf); gates via HMMA
    ln_kernel<<<MROWS / 8, 256>>>(xph, ln_g, ln_b, Abuf);
    convert_half_kernel<<<(2 * NHEAD * HID / 4) / 256, 256>>>(W_gate, Bbuf);
    gates_mma_kernel<<<MROWS / 128, 256, GATES_SMEM>>>(Abuf, Bbuf, b_gate, eig_raw, ab, bb);

    // 3) chunked scan (reference masking) -> fp16 h_all (Abuf) + h_final
    scan1_kernel<<<BNCH * NHEAD, 64>>>(ab, bb, Abuf, contrib, cum, Cc, Ee);
    scan2a_kernel<<<(BATCH * HID * 16) / 256, 256>>>(Cc, Ee, P2, E2);
    scan2b_kernel<<<(BATCH * HID) / 128, 128>>>(P2, E2, G2);
    scan2c_kernel<<<(BATCH * HID * 16) / 256, 256>>>(Cc, Ee, G2, carry);
    scan3_kernel<<<MROWS, 256>>>(cum, carry, contrib, Abuf, h_final);

    // 4) GEMM2 -> out (fp32)
    convert_half_kernel<<<(HID * HID / 4) / 256, 256>>>(W_out, Bbuf);
    mma_gemm_kernel<false><<<dim3(HID / 128, MROWS / 128), 256, GEMM_SMEM>>>(Abuf, Bbuf, out, nullptr);
}

// round 8
// speedup vs baseline: 3.1311x; 1.0492x over previous
#include <cuda_runtime.h>
#include <cuda_fp16.h>
#include <math.h>
#include <stdint.h>

// ---------------- problem constants ----------------
#define BATCH   4
#define SEQ     4096
#define HID     1024
#define NHEAD   16
#define HD      64
#define CSZ     16
#define MROWS   (BATCH*SEQ)        // 16384
#define NCHUNK  (SEQ/CSZ)          // 256
#define BNCH    (BATCH*NCHUNK)     // 1024
#define KTOT    1024               // single fp16 pass
#define BK      64                 // fp16 K per stage (128 bytes/row)
#define KI      (KTOT/BK)          // 16
#define NSTG    3                  // big-GEMM stages (96KB -> 2 CTAs/SM)
#define STG_BYTES 32768            // A 16KB + B 16KB
#define GEMM_SMEM (NSTG*STG_BYTES) // 96 KB
#define GNSTG   4                  // gates stages
#define GATES_STG 20480            // A 16KB + B 4KB
#define GATES_SMEM (GNSTG*GATES_STG)// 80 KB

// weight buffer layout (fp16): W_in | W_gate | W_out
#define WG_OFF   (HID*HID)
#define WO_OFF   (HID*HID + 2*NHEAD*HID)
#define WTOT     (2*HID*HID + 2*NHEAD*HID)   // 2,129,920 elements

// ---------------- scratch (static device globals) ----------------
__device__ __align__(16) __half g_Abuf[(size_t)MROWS*KTOT]; // 32 MB (x fp16 -> xn fp16 -> h fp16)
__device__ __align__(16) __half g_Wbuf[(size_t)WTOT];       // ~4.1 MB all weights fp16
__device__ __align__(16) __half g_xph[(size_t)MROWS*HID];   // 32 MB fp16 xp
__device__ __align__(16) __half g_contrib[(size_t)MROWS*HID]; // 32 MB fp16 contrib
__device__ float g_a[MROWS*NHEAD];
__device__ float g_beta[MROWS*NHEAD];
__device__ float g_cum[MROWS*NHEAD];
__device__ float g_C[BNCH*NHEAD];
__device__ float g_E[BNCH*HID];
__device__ float g_carry[BNCH*HID];
__device__ float g_P2[BATCH*HID*16];
__device__ float g_E2[BATCH*HID*16];
__device__ float g_G2[BATCH*HID*16];

// ---------------- PTX helpers (sm_80-level: compile-safe on compute_103) ----------------
__device__ __forceinline__ uint32_t smem_u32(const void* p) {
    uint32_t a;
    asm("{ .reg .u64 t; cvta.to.shared.u64 t, %1; cvt.u32.u64 %0, t; }" : "=r"(a) : "l"(p));
    return a;
}
#define CP_COMMIT() asm volatile("cp.async.commit_group;" ::: "memory")
#define CP_WAIT(N)  asm volatile("cp.async.wait_group %0;" :: "n"(N) : "memory")
__device__ __forceinline__ void cp_async16(uint32_t s, const void* g) {
    asm volatile("cp.async.cg.shared.global [%0], [%1], 16;" :: "r"(s), "l"(g) : "memory");
}
__device__ __forceinline__ void ldsm_x4(uint32_t& r0, uint32_t& r1, uint32_t& r2, uint32_t& r3, uint32_t addr) {
    asm volatile("ldmatrix.sync.aligned.m8n8.x4.shared.b16 {%0,%1,%2,%3}, [%4];"
                 : "=r"(r0), "=r"(r1), "=r"(r2), "=r"(r3) : "r"(addr));
}
__device__ __forceinline__ void mma16816(float& c0, float& c1, float& c2, float& c3,
                                         uint32_t a0, uint32_t a1, uint32_t a2, uint32_t a3,
                                         uint32_t b0, uint32_t b1) {
    asm volatile("mma.sync.aligned.m16n8k16.row.col.f32.f16.f16.f32 "
                 "{%0,%1,%2,%3}, {%4,%5,%6,%7}, {%8,%9}, {%0,%1,%2,%3};"
                 : "+f"(c0), "+f"(c1), "+f"(c2), "+f"(c3)
                 : "r"(a0), "r"(a1), "r"(a2), "r"(a3), "r"(b0), "r"(b1));
}
__device__ __forceinline__ uint32_t swz(uint32_t off) { return off ^ ((off >> 3) & 0x70); }

// ---------------- fp32 -> fp16 conversion (plain) ----------------
__global__ __launch_bounds__(256) void convert_half_kernel(
    const float* __restrict__ in, __half* __restrict__ out, int n4)
{
    int g = blockIdx.x * 256 + threadIdx.x;
    if (g >= n4) return;
    float4 v = reinterpret_cast<const float4*>(in)[g];
    union { __half h[4]; uint2 u; } H;
    H.h[0] = __float2half_rn(v.x);
    H.h[1] = __float2half_rn(v.y);
    H.h[2] = __float2half_rn(v.z);
    H.h[3] = __float2half_rn(v.w);
    reinterpret_cast<uint2*>(out)[g] = H.u;
}

// convert all three weight matrices in one launch
__global__ __launch_bounds__(256) void convert_weights_kernel(
    const float* __restrict__ Win, const float* __restrict__ Wg,
    const float* __restrict__ Wo, __half* __restrict__ out)
{
    int g = blockIdx.x * 256 + threadIdx.x;            // float4 index over WTOT/4
    if (g >= WTOT / 4) return;
    const float* src;
    int e = g * 4;
    if (e < WG_OFF)      src = Win + e;
    else if (e < WO_OFF) src = Wg + (e - WG_OFF);
    else                 src = Wo + (e - WO_OFF);
    float4 v = *reinterpret_cast<const float4*>(src);
    union { __half h[4]; uint2 u; } H;
    H.h[0] = __float2half_rn(v.x);
    H.h[1] = __float2half_rn(v.y);
    H.h[2] = __float2half_rn(v.z);
    H.h[3] = __float2half_rn(v.w);
    reinterpret_cast<uint2*>(out)[g] = H.u;
}

// ---------------- mma.sync fp16 GEMM: C[m,n] = sum_k A[m,k]*B[n,k], K=1024 ----------------
__device__ __forceinline__ void load_stage(const __half* Ag, const __half* Bg,
                                           uint32_t stage_base, int tid, int kit) {
    const __half* Ak = Ag + kit * BK;
    const __half* Bk = Bg + kit * BK;
    uint32_t sa = stage_base;
    uint32_t sbb = stage_base + 16384;
#pragma unroll
    for (int i = 0; i < 4; i++) {
        int u = tid + i * 256;
        int row = u >> 3, c = u & 7;
        uint32_t off = swz((uint32_t)(row * 128 + c * 16));
        cp_async16(sa  + off, Ak + (size_t)row * KTOT + c * 8);
        cp_async16(sbb + off, Bk + (size_t)row * KTOT + c * 8);
    }
}

template<bool HALF_OUT>
__global__ __launch_bounds__(256, 2) void mma_gemm_kernel(
    const __half* __restrict__ A, const __half* __restrict__ B,
    float* __restrict__ C, __half* __restrict__ Ch)
{
    extern __shared__ char smem[];
    const uint32_t sb = smem_u32(smem);
    const int tid = threadIdx.x, wid = tid >> 5, lane = tid & 31;
    const int m0 = blockIdx.y * 128;
    const int n0 = blockIdx.x * 128;
    const int warpM = (wid & 3) * 32;
    const int warpN = (wid >> 2) * 64;

    const __half* Ag = A + (size_t)m0 * KTOT;
    const __half* Bg = B + (size_t)n0 * KTOT;

    float acc[2][8][4];
#pragma unroll
    for (int mi = 0; mi < 2; mi++)
#pragma unroll
        for (int ni = 0; ni < 8; ni++)
#pragma unroll
            for (int q = 0; q < 4; q++) acc[mi][ni][q] = 0.f;

    const int arow = warpM + (lane & 15);
    const int brow = warpN + (lane & 7) + ((lane >> 4) << 3);
    const uint32_t acol_base = (uint32_t)((lane >> 4) << 4);
    const uint32_t bcol_base = (uint32_t)(((lane >> 3) & 1) << 4);

#pragma unroll
    for (int s = 0; s < NSTG - 1; s++) { load_stage(Ag, Bg, sb + s * STG_BYTES, tid, s); CP_COMMIT(); }

    for (int it = 0; it < KI; it++) {
        if (it + NSTG - 1 < KI)
            load_stage(Ag, Bg, sb + ((it + NSTG - 1) % NSTG) * STG_BYTES, tid, it + NSTG - 1);
        CP_COMMIT();
        CP_WAIT(NSTG - 1);
        __syncthreads();

        const uint32_t sa  = sb + (it % NSTG) * STG_BYTES;
        const uint32_t sbb = sa + 16384;
#pragma unroll
        for (int kk = 0; kk < 4; kk++) {
            const uint32_t kByte = (uint32_t)(kk * 32);
            uint32_t a[2][4];
#pragma unroll
            for (int mi = 0; mi < 2; mi++) {
                uint32_t off = swz((uint32_t)((arow + mi * 16) * 128) + kByte + acol_base);
                ldsm_x4(a[mi][0], a[mi][1], a[mi][2], a[mi][3], sa + off);
            }
            uint32_t b[8][2];
#pragma unroll
            for (int nb = 0; nb < 4; nb++) {
                uint32_t off = swz((uint32_t)((brow + nb * 16) * 128) + kByte + bcol_base);
                uint32_t r0, r1, r2, r3;
                ldsm_x4(r0, r1, r2, r3, sbb + off);
                b[nb * 2][0] = r0; b[nb * 2][1] = r1;
                b[nb * 2 + 1][0] = r2; b[nb * 2 + 1][1] = r3;
            }
#pragma unroll
            for (int mi = 0; mi < 2; mi++)
#pragma unroll
                for (int ni = 0; ni < 8; ni++)
                    mma16816(acc[mi][ni][0], acc[mi][ni][1], acc[mi][ni][2], acc[mi][ni][3],
                             a[mi][0], a[mi][1], a[mi][2], a[mi][3], b[ni][0], b[ni][1]);
        }
        __syncthreads();
    }

    const int crow = m0 + warpM + (lane >> 2);
    const int ccol = n0 + warpN + 2 * (lane & 3);
#pragma unroll
    for (int mi = 0; mi < 2; mi++)
#pragma unroll
        for (int ni = 0; ni < 8; ni++) {
            if (HALF_OUT) {
                __half* p0 = Ch + (size_t)(crow + mi * 16) * HID + ccol + ni * 8;
                __half* p1 = p0 + 8 * HID;
                *reinterpret_cast<__half2*>(p0) = __floats2half2_rn(acc[mi][ni][0], acc[mi][ni][1]);
                *reinterpret_cast<__half2*>(p1) = __floats2half2_rn(acc[mi][ni][2], acc[mi][ni][3]);
            } else {
                float* p0 = C + (size_t)(crow + mi * 16) * HID + ccol + ni * 8;
                float* p1 = p0 + 8 * HID;
                *reinterpret_cast<float2*>(p0) = make_float2(acc[mi][ni][0], acc[mi][ni][1]);
                *reinterpret_cast<float2*>(p1) = make_float2(acc[mi][ni][2], acc[mi][ni][3]);
            }
        }
}

// ---------------- LayerNorm (warp per row), fp16 in -> fp16 out ----------------
__global__ __launch_bounds__(256) void ln_kernel(
    const __half* __restrict__ xph, const float* __restrict__ ln_g,
    const float* __restrict__ ln_b, __half* __restrict__ xnh)
{
    int w = threadIdx.x >> 5, lane = threadIdx.x & 31;
    int row = blockIdx.x * 8 + w;
    const uint2* xr = reinterpret_cast<const uint2*>(xph + (size_t)row * HID);
    float v[8][4];
    float s = 0.f, s2 = 0.f;
#pragma unroll
    for (int i = 0; i < 8; i++) {
        union { uint2 u; __half h[4]; } U;
        U.u = xr[lane + 32 * i];
#pragma unroll
        for (int q = 0; q < 4; q++) {
            float f = __half2float(U.h[q]);
            v[i][q] = f;
            s += f; s2 += f * f;
        }
    }
#pragma unroll
    for (int o = 16; o > 0; o >>= 1) {
        s  += __shfl_xor_sync(0xffffffffu, s, o);
        s2 += __shfl_xor_sync(0xffffffffu, s2, o);
    }
    float mu = s * (1.f / HID);
    float rs = rsqrtf(s2 * (1.f / HID) - mu * mu + 1e-5f);
    uint2* xh = reinterpret_cast<uint2*>(xnh + (size_t)row * HID);
#pragma unroll
    for (int i = 0; i < 8; i++) {
        int idx = lane + 32 * i;
        float4 g4 = reinterpret_cast<const float4*>(ln_g)[idx];
        float4 b4 = reinterpret_cast<const float4*>(ln_b)[idx];
        union { uint2 u; __half2 h2[2]; } H;
        H.h2[0] = __floats2half2_rn((v[i][0] - mu) * rs * g4.x + b4.x,
                                    (v[i][1] - mu) * rs * g4.y + b4.y);
        H.h2[1] = __floats2half2_rn((v[i][2] - mu) * rs * g4.z + b4.z,
                                    (v[i][3] - mu) * rs * g4.w + b4.w);
        xh[idx] = H.u;
    }
}

// ---------------- gates via HMMA: [MROWS x 32] = xnh @ Wg^T, sigmoid fused ----------------
__device__ __forceinline__ void gates_load_stage(const __half* Ag, const __half* Bg,
                                                 uint32_t stage_base, int tid, int kit) {
    const __half* Ak = Ag + kit * BK;
    const __half* Bk = Bg + kit * BK;
    uint32_t sa = stage_base;
    uint32_t sbb = stage_base + 16384;
#pragma unroll
    for (int i = 0; i < 4; i++) {
        int u = tid + i * 256;
        int row = u >> 3, c = u & 7;
        uint32_t off = swz((uint32_t)(row * 128 + c * 16));
        cp_async16(sa + off, Ak + (size_t)row * KTOT + c * 8);
    }
    {
        int row = tid >> 3, c = tid & 7;
        uint32_t off = swz((uint32_t)(row * 128 + c * 16));
        cp_async16(sbb + off, Bk + (size_t)row * KTOT + c * 8);
    }
}

__global__ __launch_bounds__(256) void gates_mma_kernel(
    const __half* __restrict__ A, const __half* __restrict__ Wgh,
    const float* __restrict__ bg, const float* __restrict__ eig,
    float* __restrict__ a_out, float* __restrict__ beta_out)
{
    extern __shared__ char smem[];
    const uint32_t sb = smem_u32(smem);
    const int tid = threadIdx.x, wid = tid >> 5, lane = tid & 31;
    const int m0 = blockIdx.x * 128;
    const int warpM = (wid & 3) * 32;
    const int warpN = (wid >> 2) * 16;

    const __half* Ag = A + (size_t)m0 * KTOT;

    float acc[2][2][4];
#pragma unroll
    for (int mi = 0; mi < 2; mi++)
#pragma unroll
        for (int ni = 0; ni < 2; ni++)
#pragma unroll
            for (int q = 0; q < 4; q++) acc[mi][ni][q] = 0.f;

    const int arow = warpM + (lane & 15);
    const int brow = warpN + (lane & 7) + ((lane >> 4) << 3);
    const uint32_t acol_base = (uint32_t)((lane >> 4) << 4);
    const uint32_t bcol_base = (uint32_t)(((lane >> 3) & 1) << 4);

#pragma unroll
    for (int s = 0; s < GNSTG - 1; s++) { gates_load_stage(Ag, Wgh, sb + s * GATES_STG, tid, s); CP_COMMIT(); }

    for (int it = 0; it < KI; it++) {
        if (it + GNSTG - 1 < KI)
            gates_load_stage(Ag, Wgh, sb + ((it + GNSTG - 1) & 3) * GATES_STG, tid, it + GNSTG - 1);
        CP_COMMIT();
        CP_WAIT(GNSTG - 1);
        __syncthreads();

        const uint32_t sa  = sb + (it & 3) * GATES_STG;
        const uint32_t sbb = sa + 16384;
#pragma unroll
        for (int kk = 0; kk < 4; kk++) {
            const uint32_t kByte = (uint32_t)(kk * 32);
            uint32_t a[2][4];
#pragma unroll
            for (int mi = 0; mi < 2; mi++) {
                uint32_t off = swz((uint32_t)((arow + mi * 16) * 128) + kByte + acol_base);
                ldsm_x4(a[mi][0], a[mi][1], a[mi][2], a[mi][3], sa + off);
            }
            uint32_t b0, b1, b2, b3;
            {
                uint32_t off = swz((uint32_t)(brow * 128) + kByte + bcol_base);
                ldsm_x4(b0, b1, b2, b3, sbb + off);
            }
#pragma unroll
            for (int mi = 0; mi < 2; mi++) {
                mma16816(acc[mi][0][0], acc[mi][0][1], acc[mi][0][2], acc[mi][0][3],
                         a[mi][0], a[mi][1], a[mi][2], a[mi][3], b0, b1);
                mma16816(acc[mi][1][0], acc[mi][1][1], acc[mi][1][2], acc[mi][1][3],
                         a[mi][0], a[mi][1], a[mi][2], a[mi][3], b2, b3);
            }
        }
        __syncthreads();
    }

    const int crow = m0 + warpM + (lane >> 2);
    const int ccol0 = warpN + 2 * (lane & 3);
#pragma unroll
    for (int mi = 0; mi < 2; mi++)
#pragma unroll
        for (int ni = 0; ni < 2; ni++) {
            int g0 = ccol0 + ni * 8;
#pragma unroll
            for (int q = 0; q < 4; q++) {
                int g = g0 + (q & 1);
                int row = crow + mi * 16 + ((q >> 1) << 3);
                float sg = 1.f / (1.f + expf(-(acc[mi][ni][q] + bg[g])));
                if (g < 16) a_out[(size_t)row * NHEAD + g] = tanhf(eig[g]) * sg;
                else        beta_out[(size_t)row * NHEAD + (g - 16)] = sg;
            }
        }
}

// ---------------- scan pass 1: per-chunk contribution with reference masking ----------------
__global__ __launch_bounds__(64) void scan1_kernel(
    const float* __restrict__ a_buf, const float* __restrict__ beta_buf,
    const __half* __restrict__ xnh,
    __half* __restrict__ contrib, float* __restrict__ cum_out,
    float* __restrict__ Cc, float* __restrict__ Ee)
{
    const int blk = blockIdx.x;
    const int h   = blk & 15;
    const int bn  = blk >> 4;
    const int base_pos = bn * CSZ;
    const int d = threadIdx.x;

    __shared__ float s_a[CSZ], s_cum[CSZ], s_inv[CSZ], s_beta[CSZ];
    if (d < CSZ) {
        s_a[d]    = a_buf[(size_t)(base_pos + d) * NHEAD + h];
        s_beta[d] = beta_buf[(size_t)(base_pos + d) * NHEAD + h];
    }
    __syncthreads();
    if (d == 0) {
        float c = 1.f;
#pragma unroll
        for (int j = 0; j < CSZ; j++) {
            float cp = c;
            c = c * s_a[j];
            s_cum[j] = c;
            s_inv[j] = (fabsf(cp) > 1e-8f) ? (1.f / cp) : 0.f;
        }
    }
    __syncthreads();
    if (d < CSZ) cum_out[(size_t)(base_pos + d) * NHEAD + h] = s_cum[d];

    float Q = 0.f, hc = 0.f;
#pragma unroll
    for (int j = 0; j < CSZ; j++) {
        size_t idx = (size_t)(base_pos + j) * HID + h * HD + d;
        float bv = s_beta[j] * __half2float(xnh[idx]);
        hc = fmaf(s_cum[j], Q, bv);
        contrib[idx] = __float2half_rn(hc);
        Q = fmaf(bv, s_inv[j], Q);
    }
    Ee[(size_t)bn * HID + h * HD + d] = hc;
    if (d == 0) Cc[(size_t)bn * NHEAD + h] = s_cum[CSZ - 1];
}

// ---------------- scan pass 2: 3-phase group scan over 256 chunks ----------------
__global__ __launch_bounds__(256) void scan2a_kernel(
    const float* __restrict__ Cc, const float* __restrict__ Ee,
    float* __restrict__ P2, float* __restrict__ E2)
{
    int idx = blockIdx.x * 256 + threadIdx.x;
    int ch = idx & 4095, grp = idx >> 12;
    int b = ch >> 10, c = ch & 1023, h = c >> 6;
    float P = 1.f, E = 0.f;
#pragma unroll
    for (int i = 0; i < 16; i++) {
        int bn = b * NCHUNK + grp * 16 + i;
        float cc = Cc[(size_t)bn * NHEAD + h];
        E = fmaf(cc, E, Ee[(size_t)bn * HID + c]);
        P *= cc;
    }
    P2[idx] = P; E2[idx] = E;
}
__global__ __launch_bounds__(128) void scan2b_kernel(
    const float* __restrict__ P2, const float* __restrict__ E2, float* __restrict__ G2)
{
    int ch = blockIdx.x * 128 + threadIdx.x;
    float car = 0.f;
#pragma unroll
    for (int g = 0; g < 16; g++) {
        G2[g * 4096 + ch] = car;
        car = fmaf(P2[g * 4096 + ch], car, E2[g * 4096 + ch]);
    }
}
__global__ __launch_bounds__(256) void scan2c_kernel(
    const float* __restrict__ Cc, const float* __restrict__ Ee,
    const float* __restrict__ G2, float* __restrict__ carry)
{
    int idx = blockIdx.x * 256 + threadIdx.x;
    int ch = idx & 4095, grp = idx >> 12;
    int b = ch >> 10, c = ch & 1023, h = c >> 6;
    float car = G2[grp * 4096 + ch];
#pragma unroll
    for (int i = 0; i < 16; i++) {
        int bn = b * NCHUNK + grp * 16 + i;
        carry[(size_t)bn * HID + c] = car;
        car = fmaf(Cc[(size_t)bn * NHEAD + h], car, Ee[(size_t)bn * HID + c]);
    }
}

// ---------------- scan pass 3: h = cum*carry + contrib -> fp16 + h_final ----------------
__global__ __launch_bounds__(256) void scan3_kernel(
    const float* __restrict__ cum, const float* __restrict__ carry,
    const __half* __restrict__ contrib,
    __half* __restrict__ Abuf, float* __restrict__ h_final)
{
    int g = blockIdx.x * 256 + threadIdx.x;
    int pos = g >> 8;
    int c0  = (g & 255) << 2;
    int h   = c0 >> 6;
    int bn  = pos >> 4;

    float cm = cum[(size_t)pos * NHEAD + h];
    float4 cr = reinterpret_cast<const float4*>(carry + (size_t)bn * HID)[c0 >> 2];
    union { uint2 u; __half h[4]; } Cv;
    Cv.u = reinterpret_cast<const uint2*>(contrib)[g];
    float hx = fmaf(cm, cr.x, __half2float(Cv.h[0]));
    float hy = fmaf(cm, cr.y, __half2float(Cv.h[1]));
    float hz = fmaf(cm, cr.z, __half2float(Cv.h[2]));
    float hw = fmaf(cm, cr.w, __half2float(Cv.h[3]));

    union { __half h[4]; uint2 u; } H;
    H.h[0] = __float2half_rn(hx);
    H.h[1] = __float2half_rn(hy);
    H.h[2] = __float2half_rn(hz);
    H.h[3] = __float2half_rn(hw);
    reinterpret_cast<uint2*>(Abuf)[g] = H.u;

    if ((pos & (SEQ - 1)) == SEQ - 1) {
        int b = pos >> 12;
        reinterpret_cast<float4*>(h_final + (size_t)b * HID)[c0 >> 2] =
            make_float4(hx, hy, hz, hw);
    }
}

// ---------------- launch ----------------
extern "C" void kernel_launch(void* const* d_in, const int* in_sizes, int n_in,
                              void* d_out, int out_size)
{
    const float* x       = (const float*)d_in[0];
    const float* W_in    = (const float*)d_in[1];
    const float* ln_g    = (const float*)d_in[2];
    const float* ln_b    = (const float*)d_in[3];
    const float* W_gate  = (const float*)d_in[4];
    const float* b_gate  = (const float*)d_in[5];
    const float* eig_raw = (const float*)d_in[6];
    const float* W_out   = (const float*)d_in[7];

    float* out     = (float*)d_out;
    float* h_final = out + (size_t)MROWS * HID;

    __half *Abuf, *Wbuf, *xph, *contrib;
    float *ab, *bb, *cum, *Cc, *Ee, *carry, *P2, *E2, *G2;
    cudaGetSymbolAddress((void**)&Abuf,    g_Abuf);
    cudaGetSymbolAddress((void**)&Wbuf,    g_Wbuf);
    cudaGetSymbolAddress((void**)&xph,     g_xph);
    cudaGetSymbolAddress((void**)&contrib, g_contrib);
    cudaGetSymbolAddress((void**)&ab,      g_a);
    cudaGetSymbolAddress((void**)&bb,      g_beta);
    cudaGetSymbolAddress((void**)&cum,     g_cum);
    cudaGetSymbolAddress((void**)&Cc,      g_C);
    cudaGetSymbolAddress((void**)&Ee,      g_E);
    cudaGetSymbolAddress((void**)&carry,   g_carry);
    cudaGetSymbolAddress((void**)&P2,      g_P2);
    cudaGetSymbolAddress((void**)&E2,      g_E2);
    cudaGetSymbolAddress((void**)&G2,      g_G2);

    cudaFuncSetAttribute(mma_gemm_kernel<true>,  cudaFuncAttributeMaxDynamicSharedMemorySize, GEMM_SMEM);
    cudaFuncSetAttribute(mma_gemm_kernel<false>, cudaFuncAttributeMaxDynamicSharedMemorySize, GEMM_SMEM);
    cudaFuncSetAttribute(gates_mma_kernel, cudaFuncAttributeMaxDynamicSharedMemorySize, GATES_SMEM);

    // 0) all weights -> fp16 once; x -> fp16
    convert_weights_kernel<<<(WTOT / 4 + 255) / 256, 256>>>(W_in, W_gate, W_out, Wbuf);
    convert_half_kernel<<<(MROWS * HID / 4) / 256, 256>>>(x, Abuf, MROWS * HID / 4);

    // 1) GEMM1 -> xph (fp16)
    mma_gemm_kernel<true><<<dim3(HID / 128, MROWS / 128), 256, GEMM_SMEM>>>(Abuf, Wbuf, nullptr, xph);

    // 2) LN (fp16 -> fp16 xnh in Abuf); gates via HMMA
    ln_kernel<<<MROWS / 8, 256>>>(xph, ln_g, ln_b, Abuf);
    gates_mma_kernel<<<MROWS / 128, 256, GATES_SMEM>>>(Abuf, Wbuf + WG_OFF, b_gate, eig_raw, ab, bb);

    // 3) chunked scan (reference masking) -> fp16 h_all (Abuf) + h_final
    scan1_kernel<<<BNCH * NHEAD, 64>>>(ab, bb, Abuf, contrib, cum, Cc, Ee);
    scan2a_kernel<<<(BATCH * HID * 16) / 256, 256>>>(Cc, Ee, P2, E2);
    scan2b_kernel<<<(BATCH * HID) / 128, 128>>>(P2, E2, G2);
    scan2c_kernel<<<(BATCH * HID * 16) / 256, 256>>>(Cc, Ee, G2, carry);
    scan3_kernel<<<MROWS, 256>>>(cum, carry, contrib, Abuf, h_final);

    // 4) GEMM2 -> out (fp32)
    mma_gemm_kernel<false><<<dim3(HID / 128, MROWS / 128), 256, GEMM_SMEM>>>(Abuf, Wbuf + WO_OFF, out, nullptr);
}